// round 5
// baseline (speedup 1.0000x reference)
#include <cuda_runtime.h>

#define EPSF 1e-20f

// ---------------------------------------------------------------------------
// Scratch pool (static __device__ memory — no allocations allowed).
// ---------------------------------------------------------------------------
static constexpr long N512 = 2L * 32 * 512 * 512;
static constexpr long N256 = 2L * 32 * 256 * 256;
static constexpr long N128 = 2L * 32 * 128 * 128;
static constexpr long POOL_FLOATS = 6 * N512 + 2 * N256 + 2 * N128 + 4 * N256 + 256;

__device__ float g_pool[POOL_FLOATS];

// ---------------------------------------------------------------------------
// Packed f32x2 helpers
// ---------------------------------------------------------------------------
__device__ __forceinline__ unsigned long long pack2(float a, float b) {
    unsigned long long r;
    asm("mov.b64 %0, {%1, %2};" : "=l"(r) : "f"(a), "f"(b));
    return r;
}
__device__ __forceinline__ void unpack2(unsigned long long v, float& a, float& b) {
    asm("mov.b64 {%0, %1}, %2;" : "=f"(a), "=f"(b) : "l"(v));
}
__device__ __forceinline__ void ffma2(unsigned long long& acc, unsigned long long w2,
                                      unsigned long long m2) {
    asm("fma.rn.f32x2 %0, %1, %2, %0;" : "+l"(acc) : "l"(w2), "l"(m2));
}

// ---------------------------------------------------------------------------
// cp.async helpers (LDGSTS)
// ---------------------------------------------------------------------------
__device__ __forceinline__ void cp_async4(unsigned dst, const float* src, bool valid) {
    int sz = valid ? 4 : 0;
    asm volatile("cp.async.ca.shared.global [%0], [%1], 4, %2;\n"
                 :: "r"(dst), "l"(src), "r"(sz));
}
__device__ __forceinline__ void cp_commit() {
    asm volatile("cp.async.commit_group;\n");
}
template <int N>
__device__ __forceinline__ void cp_wait() {
    asm volatile("cp.async.wait_group %0;\n" :: "n"(N));
}

// ---------------------------------------------------------------------------
// Per-layer 1/sum(w): inv[l*32+co] = 1 / sum(w_l[co,:,:,:])
// ---------------------------------------------------------------------------
__global__ void wsum_kernel(const float* __restrict__ w1, const float* __restrict__ w2,
                            const float* __restrict__ w3, const float* __restrict__ w4,
                            const float* __restrict__ w5, const float* __restrict__ w6,
                            const float* __restrict__ w7, float* __restrict__ inv) {
    int l = blockIdx.x, co = threadIdx.x;
    const float* w; int n; int nco = 32;
    if      (l == 0) { w = w1; n = 1 * 25; }
    else if (l == 1) { w = w2; n = 32 * 25; }
    else if (l == 2) { w = w3; n = 32 * 25; }
    else if (l == 3) { w = w4; n = 64 * 9; }
    else if (l == 4) { w = w5; n = 64 * 9; }
    else if (l == 5) { w = w6; n = 64 * 9; }
    else             { w = w7; n = 32;  nco = 1; }
    if (co >= nco) return;
    float s = 0.f;
    for (int i = 0; i < n; i++) s += w[co * n + i];
    inv[l * 32 + co] = 1.0f / s;
}

// ---------------------------------------------------------------------------
// Fast normalized conv: KSxKS, CIN -> 32, same-padding.
// Block = 256 threads: 128 pixel-slots (32w x 4 slot-rows, 2 vertical pixels
// per slot) x 2 co-groups of 16. Raw x,c tiles double-buffered via cp.async;
// weights chunk-staged via cp.async; one barrier per input channel.
// ---------------------------------------------------------------------------
template <int CIN, int KS, int HH, int WW, int CHUNK>
__global__ __launch_bounds__(256)
void nconv_fast(const float* __restrict__ xin, const float* __restrict__ cin,
                long bstride, long cstride,
                const float* __restrict__ w, const float* __restrict__ bias,
                const float* __restrict__ winv,
                float* __restrict__ xout, float* __restrict__ cout) {
    constexpr int PAD = KS / 2, KK = KS * KS;
    constexpr int TW = 32, TH = 8;
    constexpr int SW = TW + KS - 1, SH = TH + KS - 1, NS = SH * SW;
    constexpr int NROW = KS + 1;
    __shared__ __align__(16) float ws[CHUNK * KK][32];
    __shared__ __align__(16) float cbuf[2][NS];
    __shared__ __align__(16) float xbuf[2][NS];

    const int tid = threadIdx.x;
    const int cg = tid >> 7;
    const int t = tid & 127;
    const int tx = t & 31;
    const int ry = (t >> 5) * 2;
    const int bx = blockIdx.x * TW, by = blockIdx.y * TH;
    const int b = blockIdx.z;

    unsigned long long accN[2][8], accD[2][8];
#pragma unroll
    for (int p = 0; p < 2; p++)
#pragma unroll
        for (int q = 0; q < 8; q++) { accN[p][q] = 0ULL; accD[p][q] = 0ULL; }

    const int sbase = ry * SW + tx;

    // Per-thread staging elements (<= 2 each; NS <= 512)
    const int i0 = tid, i1 = tid + 256;
    long g0 = 0, g1 = 0; bool v0 = false, v1 = false;
    {
        int r = i0 / SW, c = i0 - r * SW;
        int gy = by + r - PAD, gx = bx + c - PAD;
        v0 = (unsigned)gy < (unsigned)HH && (unsigned)gx < (unsigned)WW;
        g0 = v0 ? (long)gy * WW + gx : 0;
        if (i1 < NS) {
            r = i1 / SW; c = i1 - r * SW;
            gy = by + r - PAD; gx = bx + c - PAD;
            v1 = (unsigned)gy < (unsigned)HH && (unsigned)gx < (unsigned)WW;
            g1 = v1 ? (long)gy * WW + gx : 0;
        }
    }

    const unsigned ws_s = (unsigned)__cvta_generic_to_shared(&ws[0][0]);
    unsigned c_s[2], x_s[2];
    c_s[0] = (unsigned)__cvta_generic_to_shared(&cbuf[0][0]);
    c_s[1] = (unsigned)__cvta_generic_to_shared(&cbuf[1][0]);
    x_s[0] = (unsigned)__cvta_generic_to_shared(&xbuf[0][0]);
    x_s[1] = (unsigned)__cvta_generic_to_shared(&xbuf[1][0]);

    const float* xb = xin + (long)b * bstride;
    const float* cb = cin + (long)b * bstride;

    // Prefetch ci = 0
    {
        cp_async4(c_s[0] + i0 * 4, cb + g0, v0);
        cp_async4(x_s[0] + i0 * 4, xb + g0, v0);
        if (i1 < NS) {
            cp_async4(c_s[0] + i1 * 4, cb + g1, v1);
            cp_async4(x_s[0] + i1 * 4, xb + g1, v1);
        }
        cp_commit();
    }

#pragma unroll 1
    for (int ci = 0; ci < CIN; ci++) {
        const int bufc = ci & 1;
        const int cil = ci & (CHUNK - 1);
        cp_wait<0>();
        __syncthreads();

        if (cil == 0) {  // stage this chunk's weights (async)
            for (int i = tid; i < CHUNK * KK * 32; i += 256)
                cp_async4(ws_s + i * 4u,
                          w + ((long)(i & 31) * CIN + ci) * KK + (i >> 5), true);
            cp_commit();
        }
        if (ci + 1 < CIN) {  // prefetch next input channel
            const float* cp = cb + (long)(ci + 1) * cstride;
            const float* xp = xb + (long)(ci + 1) * cstride;
            const int nb = bufc ^ 1;
            cp_async4(c_s[nb] + i0 * 4, cp + g0, v0);
            cp_async4(x_s[nb] + i0 * 4, xp + g0, v0);
            if (i1 < NS) {
                cp_async4(c_s[nb] + i1 * 4, cp + g1, v1);
                cp_async4(x_s[nb] + i1 * 4, xp + g1, v1);
            }
            cp_commit();
        }
        if (cil == 0) {  // weights must land before compute
            if (ci + 1 < CIN) cp_wait<1>(); else cp_wait<0>();
            __syncthreads();
        }

        const float* csb = cbuf[bufc];
        const float* xsb = xbuf[bufc];
#pragma unroll
        for (int kx = 0; kx < KS; kx++) {
            unsigned long long c2[NROW], x2[NROW];
#pragma unroll
            for (int r = 0; r < NROW; r++) {
                float cv = csb[sbase + r * SW + kx];
                float xv = xsb[sbase + r * SW + kx];
                float xc = xv * cv;
                c2[r] = pack2(cv, cv);
                x2[r] = pack2(xc, xc);
            }
#pragma unroll
            for (int ky = 0; ky < KS; ky++) {
                const int kk = cil * KK + ky * KS + kx;
                const float* wrow = &ws[kk][cg * 16];
                ulonglong2 w0 = *reinterpret_cast<const ulonglong2*>(wrow);
                ulonglong2 w1 = *reinterpret_cast<const ulonglong2*>(wrow + 4);
                ulonglong2 w2 = *reinterpret_cast<const ulonglong2*>(wrow + 8);
                ulonglong2 w3 = *reinterpret_cast<const ulonglong2*>(wrow + 12);
#pragma unroll
                for (int p = 0; p < 2; p++) {
                    unsigned long long xc2 = x2[ky + p], cv2 = c2[ky + p];
                    ffma2(accN[p][0], w0.x, xc2); ffma2(accD[p][0], w0.x, cv2);
                    ffma2(accN[p][1], w0.y, xc2); ffma2(accD[p][1], w0.y, cv2);
                    ffma2(accN[p][2], w1.x, xc2); ffma2(accD[p][2], w1.x, cv2);
                    ffma2(accN[p][3], w1.y, xc2); ffma2(accD[p][3], w1.y, cv2);
                    ffma2(accN[p][4], w2.x, xc2); ffma2(accD[p][4], w2.x, cv2);
                    ffma2(accN[p][5], w2.y, xc2); ffma2(accD[p][5], w2.y, cv2);
                    ffma2(accN[p][6], w3.x, xc2); ffma2(accD[p][6], w3.x, cv2);
                    ffma2(accN[p][7], w3.y, xc2); ffma2(accD[p][7], w3.y, cv2);
                }
            }
        }
    }

    constexpr long PLANE = (long)HH * WW;
    const int xg = bx + tx;
#pragma unroll
    for (int p = 0; p < 2; p++) {
        const int yg = by + ry + p;
        const long pix = (long)yg * WW + xg;
#pragma unroll
        for (int q = 0; q < 8; q++) {
            float n0, n1, d0, d1;
            unpack2(accN[p][q], n0, n1);
            unpack2(accD[p][q], d0, d1);
            const int co0 = cg * 16 + 2 * q;
            const long o0 = ((long)b * 32 + co0) * PLANE + pix;
            xout[o0]         = n0 / (d0 + EPSF) + bias[co0];
            xout[o0 + PLANE] = n1 / (d1 + EPSF) + bias[co0 + 1];
            cout[o0]         = d0 * winv[co0];
            cout[o0 + PLANE] = d1 * winv[co0 + 1];
        }
    }
}

// ---------------------------------------------------------------------------
// Decoder fast nconv: 3x3, CIN=64 -> 32, fused concat + nearest-2x upsample,
// same cp.async double-buffered pipeline. Group flagged "half" reads half-res.
// ---------------------------------------------------------------------------
template <int HH, int WW>
__global__ __launch_bounds__(256)
void nconv_cat_fast(const float* __restrict__ x0p, const float* __restrict__ c0p, int half0,
                    const float* __restrict__ x1p, const float* __restrict__ c1p, int half1,
                    const float* __restrict__ w, const float* __restrict__ bias,
                    const float* __restrict__ winv,
                    float* __restrict__ xout, float* __restrict__ cout) {
    constexpr int KS = 3, PAD = 1, KK = 9, CIN = 64, CHUNK = 16;
    constexpr int TW = 32, TH = 8;
    constexpr int SW = TW + KS - 1, SH = TH + KS - 1, NS = SH * SW;
    constexpr int NROW = KS + 1;
    constexpr int W2 = WW / 2;
    __shared__ __align__(16) float ws[CHUNK * KK][32];
    __shared__ __align__(16) float cbuf[2][NS];
    __shared__ __align__(16) float xbuf[2][NS];

    const int tid = threadIdx.x;
    const int cg = tid >> 7;
    const int t = tid & 127;
    const int tx = t & 31;
    const int ry = (t >> 5) * 2;
    const int bx = blockIdx.x * TW, by = blockIdx.y * TH;
    const int b = blockIdx.z;

    unsigned long long accN[2][8], accD[2][8];
#pragma unroll
    for (int p = 0; p < 2; p++)
#pragma unroll
        for (int q = 0; q < 8; q++) { accN[p][q] = 0ULL; accD[p][q] = 0ULL; }

    const int sbase = ry * SW + tx;

    // Per-thread staging elements: full-res and half-res gather offsets
    const int i0 = tid, i1 = tid + 256;
    long g0F = 0, g0H = 0, g1F = 0, g1H = 0; bool v0 = false, v1 = false;
    if (i0 < NS) {
        int r = i0 / SW, c = i0 - r * SW;
        int gy = by + r - PAD, gx = bx + c - PAD;
        v0 = (unsigned)gy < (unsigned)HH && (unsigned)gx < (unsigned)WW;
        g0F = v0 ? (long)gy * WW + gx : 0;
        g0H = v0 ? (long)(gy >> 1) * W2 + (gx >> 1) : 0;
    }
    if (i1 < NS) {
        int r = i1 / SW, c = i1 - r * SW;
        int gy = by + r - PAD, gx = bx + c - PAD;
        v1 = (unsigned)gy < (unsigned)HH && (unsigned)gx < (unsigned)WW;
        g1F = v1 ? (long)gy * WW + gx : 0;
        g1H = v1 ? (long)(gy >> 1) * W2 + (gx >> 1) : 0;
    }

    const unsigned ws_s = (unsigned)__cvta_generic_to_shared(&ws[0][0]);
    unsigned c_s[2], x_s[2];
    c_s[0] = (unsigned)__cvta_generic_to_shared(&cbuf[0][0]);
    c_s[1] = (unsigned)__cvta_generic_to_shared(&cbuf[1][0]);
    x_s[0] = (unsigned)__cvta_generic_to_shared(&xbuf[0][0]);
    x_s[1] = (unsigned)__cvta_generic_to_shared(&xbuf[1][0]);

    // prefetch helper (inlined): channel ci into buffer nb
    auto prefetch = [&](int ci, int nb) {
        const int grp = ci >> 5;
        const float* xs = grp ? x1p : x0p;
        const float* cc = grp ? c1p : c0p;
        const int half = grp ? half1 : half0;
        const long plane = half ? (long)(HH / 2) * W2 : (long)HH * WW;
        const float* xp = xs + ((long)b * 32 + (ci & 31)) * plane;
        const float* cp = cc + ((long)b * 32 + (ci & 31)) * plane;
        const long o0 = half ? g0H : g0F;
        const long o1 = half ? g1H : g1F;
        if (i0 < NS) {
            cp_async4(c_s[nb] + i0 * 4, cp + o0, v0);
            cp_async4(x_s[nb] + i0 * 4, xp + o0, v0);
        }
        if (i1 < NS) {
            cp_async4(c_s[nb] + i1 * 4, cp + o1, v1);
            cp_async4(x_s[nb] + i1 * 4, xp + o1, v1);
        }
        cp_commit();
    };

    prefetch(0, 0);

#pragma unroll 1
    for (int ci = 0; ci < CIN; ci++) {
        const int bufc = ci & 1;
        const int cil = ci & (CHUNK - 1);
        cp_wait<0>();
        __syncthreads();

        if (cil == 0) {
            for (int i = tid; i < CHUNK * KK * 32; i += 256)
                cp_async4(ws_s + i * 4u,
                          w + ((long)(i & 31) * CIN + ci) * KK + (i >> 5), true);
            cp_commit();
        }
        if (ci + 1 < CIN) prefetch(ci + 1, bufc ^ 1);
        if (cil == 0) {
            if (ci + 1 < CIN) cp_wait<1>(); else cp_wait<0>();
            __syncthreads();
        }

        const float* csb = cbuf[bufc];
        const float* xsb = xbuf[bufc];
#pragma unroll
        for (int kx = 0; kx < KS; kx++) {
            unsigned long long c2[NROW], x2[NROW];
#pragma unroll
            for (int r = 0; r < NROW; r++) {
                float cv = csb[sbase + r * SW + kx];
                float xv = xsb[sbase + r * SW + kx];
                float xc = xv * cv;
                c2[r] = pack2(cv, cv);
                x2[r] = pack2(xc, xc);
            }
#pragma unroll
            for (int ky = 0; ky < KS; ky++) {
                const int kk = cil * KK + ky * KS + kx;
                const float* wrow = &ws[kk][cg * 16];
                ulonglong2 w0 = *reinterpret_cast<const ulonglong2*>(wrow);
                ulonglong2 w1 = *reinterpret_cast<const ulonglong2*>(wrow + 4);
                ulonglong2 w2 = *reinterpret_cast<const ulonglong2*>(wrow + 8);
                ulonglong2 w3 = *reinterpret_cast<const ulonglong2*>(wrow + 12);
#pragma unroll
                for (int p = 0; p < 2; p++) {
                    unsigned long long xc2 = x2[ky + p], cv2 = c2[ky + p];
                    ffma2(accN[p][0], w0.x, xc2); ffma2(accD[p][0], w0.x, cv2);
                    ffma2(accN[p][1], w0.y, xc2); ffma2(accD[p][1], w0.y, cv2);
                    ffma2(accN[p][2], w1.x, xc2); ffma2(accD[p][2], w1.x, cv2);
                    ffma2(accN[p][3], w1.y, xc2); ffma2(accD[p][3], w1.y, cv2);
                    ffma2(accN[p][4], w2.x, xc2); ffma2(accD[p][4], w2.x, cv2);
                    ffma2(accN[p][5], w2.y, xc2); ffma2(accD[p][5], w2.y, cv2);
                    ffma2(accN[p][6], w3.x, xc2); ffma2(accD[p][6], w3.x, cv2);
                    ffma2(accN[p][7], w3.y, xc2); ffma2(accD[p][7], w3.y, cv2);
                }
            }
        }
    }

    constexpr long PLANE = (long)HH * WW;
    const int xg = bx + tx;
#pragma unroll
    for (int p = 0; p < 2; p++) {
        const int yg = by + ry + p;
        const long pix = (long)yg * WW + xg;
#pragma unroll
        for (int q = 0; q < 8; q++) {
            float n0, n1, d0, d1;
            unpack2(accN[p][q], n0, n1);
            unpack2(accD[p][q], d0, d1);
            const int co0 = cg * 16 + 2 * q;
            const long o0 = ((long)b * 32 + co0) * PLANE + pix;
            xout[o0]         = n0 / (d0 + EPSF) + bias[co0];
            xout[o0 + PLANE] = n1 / (d1 + EPSF) + bias[co0 + 1];
            cout[o0]         = d0 * winv[co0];
            cout[o0 + PLANE] = d1 * winv[co0 + 1];
        }
    }
}

// ---------------------------------------------------------------------------
// 2x2 stride-2 confidence-argmax pool (first-occurrence argmax like jnp).
// ---------------------------------------------------------------------------
__global__ void pool_kernel(const float* __restrict__ xin, const float* __restrict__ cin,
                            float* __restrict__ xout, float* __restrict__ cout,
                            int Ho, int Wo) {
    long i = (long)blockIdx.x * blockDim.x + threadIdx.x;
    long total = 64L * Ho * Wo;
    if (i >= total) return;
    int xo = (int)(i % Wo);
    long t = i / Wo;
    int yo = (int)(t % Ho);
    long bc = t / Ho;
    const int Wi = 2 * Wo;
    long ib = bc * 4L * Ho * Wo + (long)(2 * yo) * Wi + 2 * xo;
    float c00 = cin[ib], c01 = cin[ib + 1], c10 = cin[ib + Wi], c11 = cin[ib + Wi + 1];
    float best = c00; int bi = 0;
    if (c01 > best) { best = c01; bi = 1; }
    if (c10 > best) { best = c10; bi = 2; }
    if (c11 > best) { best = c11; bi = 3; }
    long off = (long)(bi >> 1) * Wi + (bi & 1);
    xout[i] = xin[ib + off];
    cout[i] = best * 0.25f;
}

// ---------------------------------------------------------------------------
// Final 1x1 nconv (32 -> 1)
// ---------------------------------------------------------------------------
__global__ void final1x1_kernel(const float* __restrict__ xin, const float* __restrict__ cin,
                                const float* __restrict__ w7, const float* __restrict__ b7,
                                float* __restrict__ out) {
    constexpr long HW = 512L * 512L;
    long i = (long)blockIdx.x * blockDim.x + threadIdx.x;
    if (i >= 2 * HW) return;
    int b = (int)(i / HW);
    long p = i - (long)b * HW;
    const float* xb = xin + (long)b * 32 * HW + p;
    const float* cb = cin + (long)b * 32 * HW + p;
    float n = 0.f, d = 0.f;
#pragma unroll
    for (int ci = 0; ci < 32; ci++) {
        float wv = __ldg(w7 + ci);
        float cv = __ldg(cb + (long)ci * HW);
        float xv = __ldg(xb + (long)ci * HW);
        n += wv * xv * cv;
        d += wv * cv;
    }
    out[i] = n / (d + EPSF) + __ldg(b7);
}

// ---------------------------------------------------------------------------
// Launch sequence
// ---------------------------------------------------------------------------
extern "C" void kernel_launch(void* const* d_in, const int* in_sizes, int n_in,
                              void* d_out, int out_size) {
    const float* x  = (const float*)d_in[0];
    const float* w1 = (const float*)d_in[1];  const float* b1 = (const float*)d_in[2];
    const float* w2 = (const float*)d_in[3];  const float* b2 = (const float*)d_in[4];
    const float* w3 = (const float*)d_in[5];  const float* b3 = (const float*)d_in[6];
    const float* w4 = (const float*)d_in[7];  const float* b4 = (const float*)d_in[8];
    const float* w5 = (const float*)d_in[9];  const float* b5 = (const float*)d_in[10];
    const float* w6 = (const float*)d_in[11]; const float* b6 = (const float*)d_in[12];
    const float* w7 = (const float*)d_in[13]; const float* b7 = (const float*)d_in[14];

    float* pool = nullptr;
    cudaGetSymbolAddress((void**)&pool, g_pool);

    float* P0x = pool;
    float* P0c = pool + N512;
    float* P1x = pool + 2 * N512;
    float* P1c = pool + 3 * N512;
    float* X1  = pool + 4 * N512;
    float* C1  = pool + 5 * N512;
    float* X2  = pool + 6 * N512;
    float* C2  = X2 + N256;
    float* X3  = C2 + N256;
    float* C3  = X3 + N128;
    float* S0x = C3 + N128;
    float* S0c = S0x + N256;
    float* S1x = S0c + N256;
    float* S1c = S1x + N256;
    float* WS  = S1c + N256;

    const long HW = 512L * 512;

    wsum_kernel<<<7, 32>>>(w1, w2, w3, w4, w5, w6, w7, WS);

    // Encoder full-res: L1 (1->32), L2, L3 @512
    nconv_fast<1, 5, 512, 512, 1><<<dim3(16, 64, 2), 256>>>(
        x, x + HW, 2 * HW, HW, w1, b1, WS + 0, P0x, P0c);
    nconv_fast<32, 5, 512, 512, 8><<<dim3(16, 64, 2), 256>>>(
        P0x, P0c, 32 * HW, HW, w2, b2, WS + 32, P1x, P1c);
    nconv_fast<32, 5, 512, 512, 8><<<dim3(16, 64, 2), 256>>>(
        P1x, P1c, 32 * HW, HW, w3, b3, WS + 64, X1, C1);

    // Down 1: pool 512->256, L2, L3 @256
    pool_kernel<<<(int)((64L * 256 * 256 + 255) / 256), 256>>>(X1, C1, S0x, S0c, 256, 256);
    nconv_fast<32, 5, 256, 256, 8><<<dim3(8, 32, 2), 256>>>(
        S0x, S0c, 32L * 256 * 256, 256L * 256, w2, b2, WS + 32, S1x, S1c);
    nconv_fast<32, 5, 256, 256, 8><<<dim3(8, 32, 2), 256>>>(
        S1x, S1c, 32L * 256 * 256, 256L * 256, w3, b3, WS + 64, X2, C2);

    // Down 2: pool 256->128, L2 @128
    pool_kernel<<<(int)((64L * 128 * 128 + 255) / 256), 256>>>(X2, C2, S0x, S0c, 128, 128);
    nconv_fast<32, 5, 128, 128, 8><<<dim3(4, 16, 2), 256>>>(
        S0x, S0c, 32L * 128 * 128, 128L * 128, w2, b2, WS + 32, X3, C3);

    // Down 3: pool 128->64, L2 @64
    pool_kernel<<<(int)((64L * 64 * 64 + 255) / 256), 256>>>(X3, C3, S1x, S1c, 64, 64);
    nconv_fast<32, 5, 64, 64, 8><<<dim3(2, 8, 2), 256>>>(
        S1x, S1c, 32L * 64 * 64, 64L * 64, w2, b2, WS + 32, S0x, S0c);

    // Decoder
    nconv_cat_fast<128, 128><<<dim3(4, 16, 2), 256>>>(
        X3, C3, 0, S0x, S0c, 1, w4, b4, WS + 96, S1x, S1c);
    nconv_cat_fast<256, 256><<<dim3(8, 32, 2), 256>>>(
        X2, C2, 0, S1x, S1c, 1, w5, b5, WS + 128, S0x, S0c);
    nconv_cat_fast<512, 512><<<dim3(16, 64, 2), 256>>>(
        S0x, S0c, 1, X1, C1, 0, w6, b6, WS + 160, P0x, P0c);

    final1x1_kernel<<<2048, 256>>>(P0x, P0c, w7, b7, (float*)d_out);
}

// round 6
// speedup vs baseline: 3.2145x; 3.2145x over previous
#include <cuda_runtime.h>
#define EPSF 1e-20f

static constexpr long N512 = 2L * 32 * 512 * 512;
static constexpr long N256 = 2L * 32 * 256 * 256;
static constexpr long N128 = 2L * 32 * 128 * 128;
static constexpr long WP5 = 4L * 25 * 256;   // 25600 floats per 5x5 layer
static constexpr long WP3 = 8L * 9 * 256;    // 18432 floats per 3x3 layer
static constexpr long POOL_FLOATS =
    6 * N512 + 2 * N256 + 2 * N128 + 4 * N256 + 256 + 2 * WP5 + 3 * WP3;

__device__ __align__(16) float g_pool[POOL_FLOATS];

// ---------------- helpers ----------------
__device__ __forceinline__ unsigned long long pack2(float a, float b) {
    unsigned long long r;
    asm("mov.b64 %0, {%1, %2};" : "=l"(r) : "f"(a), "f"(b));
    return r;
}
__device__ __forceinline__ void unpack2(unsigned long long v, float& a, float& b) {
    asm("mov.b64 {%0, %1}, %2;" : "=f"(a), "=f"(b) : "l"(v));
}
__device__ __forceinline__ void ffma2(unsigned long long& acc, unsigned long long w2,
                                      unsigned long long m2) {
    asm("fma.rn.f32x2 %0, %1, %2, %0;" : "+l"(acc) : "l"(w2), "l"(m2));
}
__device__ __forceinline__ void cp_async4(unsigned dst, const float* src, bool valid) {
    int sz = valid ? 4 : 0;
    asm volatile("cp.async.ca.shared.global [%0], [%1], 4, %2;\n"
                 :: "r"(dst), "l"(src), "r"(sz));
}
__device__ __forceinline__ void cp_async16(unsigned dst, const float* src) {
    asm volatile("cp.async.ca.shared.global [%0], [%1], 16;\n" :: "r"(dst), "l"(src));
}
__device__ __forceinline__ void cp_commit() { asm volatile("cp.async.commit_group;\n"); }
template <int N>
__device__ __forceinline__ void cp_wait() {
    asm volatile("cp.async.wait_group %0;\n" :: "n"(N));
}
__device__ __forceinline__ unsigned f2tf32(float f) {
    unsigned r;
    asm("cvt.rna.tf32.f32 %0, %1;" : "=r"(r) : "f"(f));
    return r;
}
__device__ __forceinline__ void mma8(float* d, unsigned a0, unsigned a1,
                                     unsigned a2, unsigned a3, unsigned b0, unsigned b1) {
    asm("mma.sync.aligned.m16n8k8.row.col.f32.tf32.tf32.f32 "
        "{%0,%1,%2,%3},{%4,%5,%6,%7},{%8,%9},{%0,%1,%2,%3};"
        : "+f"(d[0]), "+f"(d[1]), "+f"(d[2]), "+f"(d[3])
        : "r"(a0), "r"(a1), "r"(a2), "r"(a3), "r"(b0), "r"(b1));
}

// pack raw (x,c) -> permuted tf32 (x*c, c); slot s holds ci = (s&1)*4 + s/2
__device__ __forceinline__ void pack8(const float* rawx, const float* rawc,
                                      unsigned* pxc, unsigned* pc, int NS, int tid) {
    for (int p = tid; p < NS; p += 256) {
        float cv[8], xc[8];
#pragma unroll
        for (int ci = 0; ci < 8; ci++) {
            cv[ci] = rawc[ci * NS + p];
            xc[ci] = rawx[ci * NS + p] * cv[ci];
        }
        uint4 a, b;
        a.x = f2tf32(xc[0]); a.y = f2tf32(xc[4]); a.z = f2tf32(xc[1]); a.w = f2tf32(xc[5]);
        b.x = f2tf32(xc[2]); b.y = f2tf32(xc[6]); b.z = f2tf32(xc[3]); b.w = f2tf32(xc[7]);
        *reinterpret_cast<uint4*>(pxc + p * 8) = a;
        *reinterpret_cast<uint4*>(pxc + p * 8 + 4) = b;
        a.x = f2tf32(cv[0]); a.y = f2tf32(cv[4]); a.z = f2tf32(cv[1]); a.w = f2tf32(cv[5]);
        b.x = f2tf32(cv[2]); b.y = f2tf32(cv[6]); b.z = f2tf32(cv[3]); b.w = f2tf32(cv[7]);
        *reinterpret_cast<uint4*>(pc + p * 8) = a;
        *reinterpret_cast<uint4*>(pc + p * 8 + 4) = b;
    }
}

template <int KS, int SW>
__device__ __forceinline__ void mma_taps(const unsigned* wc, const unsigned* pxcw,
                                         const unsigned* pcw,
                                         float (&accN)[2][4][4], float (&accD)[2][4][4]) {
#pragma unroll
    for (int ky = 0; ky < KS; ky++)
#pragma unroll
        for (int kx = 0; kx < KS; kx++) {
            const int kk = ky * KS + kx;
            uint2 b[4];
#pragma unroll
            for (int nf = 0; nf < 4; nf++)
                b[nf] = *reinterpret_cast<const uint2*>(wc + kk * 256 + nf * 64);
#pragma unroll
            for (int mf = 0; mf < 2; mf++) {
                const int off = (ky * SW + mf * 16 + kx) * 8;
                uint2 x0 = *reinterpret_cast<const uint2*>(pxcw + off);
                uint2 x1 = *reinterpret_cast<const uint2*>(pxcw + off + 64);
                uint2 c0 = *reinterpret_cast<const uint2*>(pcw + off);
                uint2 c1 = *reinterpret_cast<const uint2*>(pcw + off + 64);
#pragma unroll
                for (int nf = 0; nf < 4; nf++) {
                    mma8(accN[mf][nf], x0.x, x1.x, x0.y, x1.y, b[nf].x, b[nf].y);
                    mma8(accD[mf][nf], c0.x, c1.x, c0.y, c1.y, b[nf].x, b[nf].y);
                }
            }
        }
}

__device__ __forceinline__ void epi(float (&aN)[2][4][4], float (&aD)[2][4][4],
                                    const float* bias, const float* winv,
                                    float* xout, float* cout, long PLANE, int WW,
                                    int bz, int y, int bx, int g, int t) {
#pragma unroll
    for (int mf = 0; mf < 2; mf++)
#pragma unroll
        for (int nf = 0; nf < 4; nf++) {
            const int co = nf * 8 + 2 * t;
            const int px = bx + mf * 16 + g;
            const long base = ((long)bz * 32 + co) * PLANE + (long)y * WW;
            float* n = aN[mf][nf];
            float* d = aD[mf][nf];
            xout[base + px]             = n[0] / (d[0] + EPSF) + bias[co];
            xout[base + PLANE + px]     = n[1] / (d[1] + EPSF) + bias[co + 1];
            xout[base + px + 8]         = n[2] / (d[2] + EPSF) + bias[co];
            xout[base + PLANE + px + 8] = n[3] / (d[3] + EPSF) + bias[co + 1];
            cout[base + px]             = d[0] * winv[co];
            cout[base + PLANE + px]     = d[1] * winv[co + 1];
            cout[base + px + 8]         = d[2] * winv[co];
            cout[base + PLANE + px + 8] = d[3] * winv[co + 1];
        }
}

// ---------------- small kernels ----------------
__global__ void wsum_kernel(const float* __restrict__ w1, const float* __restrict__ w2,
                            const float* __restrict__ w3, const float* __restrict__ w4,
                            const float* __restrict__ w5, const float* __restrict__ w6,
                            const float* __restrict__ w7, float* __restrict__ inv) {
    int l = blockIdx.x, co = threadIdx.x;
    const float* w; int n; int nco = 32;
    if      (l == 0) { w = w1; n = 1 * 25; }
    else if (l == 1) { w = w2; n = 32 * 25; }
    else if (l == 2) { w = w3; n = 32 * 25; }
    else if (l == 3) { w = w4; n = 64 * 9; }
    else if (l == 4) { w = w5; n = 64 * 9; }
    else if (l == 5) { w = w6; n = 64 * 9; }
    else             { w = w7; n = 32;  nco = 1; }
    if (co >= nco) return;
    float s = 0.f;
    for (int i = 0; i < n; i++) s += w[co * n + i];
    inv[l * 32 + co] = 1.0f / s;
}

// weight prep: OIHW -> [chunk][kk][co32][slot8], tf32-rounded
__global__ void prep_w(const float* __restrict__ w, float* __restrict__ dst,
                       int CIN, int KK, int total) {
    int i = blockIdx.x * 256 + threadIdx.x;
    if (i >= total) return;
    int pos = i & 7;
    int co = (i >> 3) & 31;
    int r = i >> 8;
    int kk = r % KK, chunk = r / KK;
    int ci = chunk * 8 + ((pos & 1) ? (pos >> 1) + 4 : (pos >> 1));
    dst[i] = __uint_as_float(f2tf32(w[((long)co * CIN + ci) * KK + kk]));
}

__global__ void pool_kernel(const float* __restrict__ xin, const float* __restrict__ cin,
                            float* __restrict__ xout, float* __restrict__ cout,
                            int Ho, int Wo) {
    long i = (long)blockIdx.x * blockDim.x + threadIdx.x;
    long total = 64L * Ho * Wo;
    if (i >= total) return;
    int xo = (int)(i % Wo);
    long t = i / Wo;
    int yo = (int)(t % Ho);
    long bc = t / Ho;
    const int Wi = 2 * Wo;
    long ib = bc * 4L * Ho * Wo + (long)(2 * yo) * Wi + 2 * xo;
    float c00 = cin[ib], c01 = cin[ib + 1], c10 = cin[ib + Wi], c11 = cin[ib + Wi + 1];
    float best = c00; int bi = 0;
    if (c01 > best) { best = c01; bi = 1; }
    if (c10 > best) { best = c10; bi = 2; }
    if (c11 > best) { best = c11; bi = 3; }
    long off = (long)(bi >> 1) * Wi + (bi & 1);
    xout[i] = xin[ib + off];
    cout[i] = best * 0.25f;
}

__global__ void final1x1_kernel(const float* __restrict__ xin, const float* __restrict__ cin,
                                const float* __restrict__ w7, const float* __restrict__ b7,
                                float* __restrict__ out) {
    constexpr long HW = 512L * 512L;
    long i = (long)blockIdx.x * blockDim.x + threadIdx.x;
    if (i >= 2 * HW) return;
    int b = (int)(i / HW);
    long p = i - (long)b * HW;
    const float* xb = xin + (long)b * 32 * HW + p;
    const float* cb = cin + (long)b * 32 * HW + p;
    float n = 0.f, d = 0.f;
#pragma unroll
    for (int ci = 0; ci < 32; ci++) {
        float wv = __ldg(w7 + ci);
        float cv = __ldg(cb + (long)ci * HW);
        float xv = __ldg(xb + (long)ci * HW);
        n += wv * xv * cv;
        d += wv * cv;
    }
    out[i] = n / (d + EPSF) + __ldg(b7);
}

// layer1 scalar nconv: 5x5, CIN=1 -> 32
template <int HH, int WW>
__global__ __launch_bounds__(256)
void nconv_l1(const float* __restrict__ xin, const float* __restrict__ cin, long bstride,
              const float* __restrict__ w, const float* __restrict__ bias,
              const float* __restrict__ winv,
              float* __restrict__ xout, float* __restrict__ cout) {
    constexpr int PAD = 2, SW = 36, SH = 12, NS = SW * SH;
    constexpr long PLANE = (long)HH * WW;
    __shared__ __align__(16) float ws[25][32];
    __shared__ float cs[NS], xcs[NS];
    const int tid = threadIdx.x, tx = tid & 31, ty = tid >> 5;
    const int bx = blockIdx.x * 32, by = blockIdx.y * 8, b = blockIdx.z;
    for (int i = tid; i < 800; i += 256) ws[i >> 5][i & 31] = w[(i & 31) * 25 + (i >> 5)];
    const float* xp = xin + (long)b * bstride;
    const float* cp = cin + (long)b * bstride;
    for (int i = tid; i < NS; i += 256) {
        int r = i / SW, c = i - r * SW;
        int gy = by + r - PAD, gx = bx + c - PAD;
        float cv = 0.f, xv = 0.f;
        if ((unsigned)gy < (unsigned)HH && (unsigned)gx < (unsigned)WW) {
            long gg = (long)gy * WW + gx;
            cv = cp[gg]; xv = xp[gg];
        }
        cs[i] = cv; xcs[i] = xv * cv;
    }
    __syncthreads();
    unsigned long long accN[16], accD[16];
#pragma unroll
    for (int q = 0; q < 16; q++) { accN[q] = 0ULL; accD[q] = 0ULL; }
#pragma unroll
    for (int ky = 0; ky < 5; ky++)
#pragma unroll
        for (int kx = 0; kx < 5; kx++) {
            float cv = cs[(ty + ky) * SW + tx + kx];
            float xc = xcs[(ty + ky) * SW + tx + kx];
            unsigned long long c2 = pack2(cv, cv), x2 = pack2(xc, xc);
            const float* wr = &ws[ky * 5 + kx][0];
#pragma unroll
            for (int q = 0; q < 8; q++) {
                ulonglong2 wv = *reinterpret_cast<const ulonglong2*>(wr + q * 4);
                ffma2(accN[2 * q], wv.x, x2);     ffma2(accD[2 * q], wv.x, c2);
                ffma2(accN[2 * q + 1], wv.y, x2); ffma2(accD[2 * q + 1], wv.y, c2);
            }
        }
    const long pix = (long)(by + ty) * WW + bx + tx;
#pragma unroll
    for (int q = 0; q < 16; q++) {
        float n0, n1, d0, d1;
        unpack2(accN[q], n0, n1); unpack2(accD[q], d0, d1);
        const int co = 2 * q;
        const long o = ((long)b * 32 + co) * PLANE + pix;
        xout[o]         = n0 / (d0 + EPSF) + bias[co];
        xout[o + PLANE] = n1 / (d1 + EPSF) + bias[co + 1];
        cout[o]         = d0 * winv[co];
        cout[o + PLANE] = d1 * winv[co + 1];
    }
}

// ---------------- tensor-core encoder nconv: 5x5, 32->32 ----------------
template <int HH, int WW>
__global__ __launch_bounds__(256, 2)
void nconv_mma(const float* __restrict__ xin, const float* __restrict__ cin,
               const float* __restrict__ wp, const float* __restrict__ bias,
               const float* __restrict__ winv,
               float* __restrict__ xout, float* __restrict__ cout) {
    constexpr int KS = 5, PAD = 2, KK = 25, SW = 36, SH = 12, NS = SH * SW;
    constexpr int NCH = 4, WCH = KK * 256;
    constexpr long PLANE = (long)HH * WW;
    extern __shared__ float dsm[];
    float* rawx = dsm;
    float* rawc = rawx + 8 * NS;
    unsigned* pxc = (unsigned*)(rawc + 8 * NS);
    unsigned* pc  = pxc + 8 * NS;
    unsigned* wsb = pc + 8 * NS;

    const int tid = threadIdx.x, wy = tid >> 5, lane = tid & 31;
    const int g = lane >> 2, t = lane & 3;
    const int bx = blockIdx.x * 32, by = blockIdx.y * 8, bz = blockIdx.z;

    const int p0 = tid, p1 = tid + 256;
    long g0 = 0, g1 = 0; bool v0 = false, v1 = false;
    {
        int r = p0 / SW, c = p0 - r * SW;
        int gy = by + r - PAD, gx = bx + c - PAD;
        v0 = (unsigned)gy < (unsigned)HH && (unsigned)gx < (unsigned)WW;
        g0 = v0 ? (long)gy * WW + gx : 0;
    }
    if (p1 < NS) {
        int r = p1 / SW, c = p1 - r * SW;
        int gy = by + r - PAD, gx = bx + c - PAD;
        v1 = (unsigned)gy < (unsigned)HH && (unsigned)gx < (unsigned)WW;
        g1 = v1 ? (long)gy * WW + gx : 0;
    }
    const float* xb = xin + (long)bz * 32 * PLANE;
    const float* cb = cin + (long)bz * 32 * PLANE;
    const unsigned rx_s = (unsigned)__cvta_generic_to_shared(rawx);
    const unsigned rc_s = (unsigned)__cvta_generic_to_shared(rawc);
    const unsigned ws_s = (unsigned)__cvta_generic_to_shared(wsb);

    auto stage_raw = [&](int ch) {
#pragma unroll
        for (int ci = 0; ci < 8; ci++) {
            const float* xp = xb + (long)(ch * 8 + ci) * PLANE;
            const float* cp = cb + (long)(ch * 8 + ci) * PLANE;
            cp_async4(rx_s + (ci * NS + p0) * 4, xp + g0, v0);
            cp_async4(rc_s + (ci * NS + p0) * 4, cp + g0, v0);
            if (p1 < NS) {
                cp_async4(rx_s + (ci * NS + p1) * 4, xp + g1, v1);
                cp_async4(rc_s + (ci * NS + p1) * 4, cp + g1, v1);
            }
        }
    };
    auto stage_w = [&](int ch) {
        const float* src = wp + (long)ch * WCH;
        const unsigned dst = ws_s + ((ch & 1) * WCH) * 4;
        for (int i = tid; i < WCH / 4; i += 256) cp_async16(dst + i * 16, src + i * 4);
    };

    stage_raw(0); stage_w(0); cp_commit();

    float accN[2][4][4] = {}, accD[2][4][4] = {};
    const int abase = g * 8 + 2 * t;

#pragma unroll 1
    for (int ch = 0; ch < NCH; ch++) {
        cp_wait<0>();
        __syncthreads();
        pack8(rawx, rawc, pxc, pc, NS, tid);
        __syncthreads();
        if (ch + 1 < NCH) { stage_raw(ch + 1); stage_w(ch + 1); cp_commit(); }
        mma_taps<KS, SW>(wsb + (ch & 1) * WCH + abase,
                         pxc + wy * SW * 8 + abase, pc + wy * SW * 8 + abase, accN, accD);
    }
    epi(accN, accD, bias, winv, xout, cout, PLANE, WW, bz, by + wy, bx, g, t);
}

// ------------- tensor-core decoder nconv: 3x3, 64->32, cat + up2 -------------
template <int HH, int WW>
__global__ __launch_bounds__(256, 2)
void nconv_cat_mma(const float* __restrict__ x0p, const float* __restrict__ c0p, int half0,
                   const float* __restrict__ x1p, const float* __restrict__ c1p, int half1,
                   const float* __restrict__ wp, const float* __restrict__ bias,
                   const float* __restrict__ winv,
                   float* __restrict__ xout, float* __restrict__ cout) {
    constexpr int KS = 3, PAD = 1, KK = 9, SW = 34, SH = 10, NS = SH * SW;
    constexpr int NCH = 8, WCH = KK * 256;
    constexpr int W2 = WW / 2;
    constexpr long PLANE = (long)HH * WW;
    extern __shared__ float dsm[];
    float* rawx = dsm;
    float* rawc = rawx + 8 * NS;
    unsigned* pxc = (unsigned*)(rawc + 8 * NS);
    unsigned* pc  = pxc + 8 * NS;
    unsigned* wsb = pc + 8 * NS;

    const int tid = threadIdx.x, wy = tid >> 5, lane = tid & 31;
    const int g = lane >> 2, t = lane & 3;
    const int bx = blockIdx.x * 32, by = blockIdx.y * 8, bz = blockIdx.z;

    const int p0 = tid, p1 = tid + 256;
    long g0F = 0, g0H = 0, g1F = 0, g1H = 0; bool v0 = false, v1 = false;
    {
        int r = p0 / SW, c = p0 - r * SW;
        int gy = by + r - PAD, gx = bx + c - PAD;
        v0 = (unsigned)gy < (unsigned)HH && (unsigned)gx < (unsigned)WW;
        g0F = v0 ? (long)gy * WW + gx : 0;
        g0H = v0 ? (long)(gy >> 1) * W2 + (gx >> 1) : 0;
    }
    if (p1 < NS) {
        int r = p1 / SW, c = p1 - r * SW;
        int gy = by + r - PAD, gx = bx + c - PAD;
        v1 = (unsigned)gy < (unsigned)HH && (unsigned)gx < (unsigned)WW;
        g1F = v1 ? (long)gy * WW + gx : 0;
        g1H = v1 ? (long)(gy >> 1) * W2 + (gx >> 1) : 0;
    }
    const unsigned rx_s = (unsigned)__cvta_generic_to_shared(rawx);
    const unsigned rc_s = (unsigned)__cvta_generic_to_shared(rawc);
    const unsigned ws_s = (unsigned)__cvta_generic_to_shared(wsb);

    auto stage_raw = [&](int ch) {
        const int grp = ch >> 2;
        const float* xs = grp ? x1p : x0p;
        const float* cc = grp ? c1p : c0p;
        const int half = grp ? half1 : half0;
        const long plane = half ? (long)(HH / 2) * W2 : PLANE;
        const long o0 = half ? g0H : g0F;
        const long o1 = half ? g1H : g1F;
#pragma unroll
        for (int ci = 0; ci < 8; ci++) {
            const float* xp = xs + ((long)bz * 32 + (ch & 3) * 8 + ci) * plane;
            const float* cp = cc + ((long)bz * 32 + (ch & 3) * 8 + ci) * plane;
            cp_async4(rx_s + (ci * NS + p0) * 4, xp + o0, v0);
            cp_async4(rc_s + (ci * NS + p0) * 4, cp + o0, v0);
            if (p1 < NS) {
                cp_async4(rx_s + (ci * NS + p1) * 4, xp + o1, v1);
                cp_async4(rc_s + (ci * NS + p1) * 4, cp + o1, v1);
            }
        }
    };
    auto stage_w = [&](int ch) {
        const float* src = wp + (long)ch * WCH;
        const unsigned dst = ws_s + ((ch & 1) * WCH) * 4;
        for (int i = tid; i < WCH / 4; i += 256) cp_async16(dst + i * 16, src + i * 4);
    };

    stage_raw(0); stage_w(0); cp_commit();

    float accN[2][4][4] = {}, accD[2][4][4] = {};
    const int abase = g * 8 + 2 * t;

#pragma unroll 1
    for (int ch = 0; ch < NCH; ch++) {
        cp_wait<0>();
        __syncthreads();
        pack8(rawx, rawc, pxc, pc, NS, tid);
        __syncthreads();
        if (ch + 1 < NCH) { stage_raw(ch + 1); stage_w(ch + 1); cp_commit(); }
        mma_taps<KS, SW>(wsb + (ch & 1) * WCH + abase,
                         pxc + wy * SW * 8 + abase, pc + wy * SW * 8 + abase, accN, accD);
    }
    epi(accN, accD, bias, winv, xout, cout, PLANE, WW, bz, by + wy, bx, g, t);
}

// ---------------- launch ----------------
static constexpr int SMEM_ENC = (16 * 432 + 16 * 432 + 2 * 25 * 256) * 4;  // 106496
static constexpr int SMEM_DEC = (16 * 340 + 16 * 340 + 2 * 9 * 256) * 4;   // 61952

extern "C" void kernel_launch(void* const* d_in, const int* in_sizes, int n_in,
                              void* d_out, int out_size) {
    const float* x  = (const float*)d_in[0];
    const float* w1 = (const float*)d_in[1];  const float* b1 = (const float*)d_in[2];
    const float* w2 = (const float*)d_in[3];  const float* b2 = (const float*)d_in[4];
    const float* w3 = (const float*)d_in[5];  const float* b3 = (const float*)d_in[6];
    const float* w4 = (const float*)d_in[7];  const float* b4 = (const float*)d_in[8];
    const float* w5 = (const float*)d_in[9];  const float* b5 = (const float*)d_in[10];
    const float* w6 = (const float*)d_in[11]; const float* b6 = (const float*)d_in[12];
    const float* w7 = (const float*)d_in[13]; const float* b7 = (const float*)d_in[14];

    float* pool = nullptr;
    cudaGetSymbolAddress((void**)&pool, g_pool);

    float* P0x = pool;
    float* P0c = pool + N512;
    float* P1x = pool + 2 * N512;
    float* P1c = pool + 3 * N512;
    float* X1  = pool + 4 * N512;
    float* C1  = pool + 5 * N512;
    float* X2  = pool + 6 * N512;
    float* C2  = X2 + N256;
    float* X3  = C2 + N256;
    float* C3  = X3 + N128;
    float* S0x = C3 + N128;
    float* S0c = S0x + N256;
    float* S1x = S0c + N256;
    float* S1c = S1x + N256;
    float* WS  = S1c + N256;
    float* PW2 = WS + 256;
    float* PW3 = PW2 + WP5;
    float* PW4 = PW3 + WP5;
    float* PW5 = PW4 + WP3;
    float* PW6 = PW5 + WP3;

    cudaFuncSetAttribute(nconv_mma<512, 512>, cudaFuncAttributeMaxDynamicSharedMemorySize, SMEM_ENC);
    cudaFuncSetAttribute(nconv_mma<256, 256>, cudaFuncAttributeMaxDynamicSharedMemorySize, SMEM_ENC);
    cudaFuncSetAttribute(nconv_mma<128, 128>, cudaFuncAttributeMaxDynamicSharedMemorySize, SMEM_ENC);
    cudaFuncSetAttribute(nconv_mma<64, 64>,   cudaFuncAttributeMaxDynamicSharedMemorySize, SMEM_ENC);
    cudaFuncSetAttribute(nconv_cat_mma<128, 128>, cudaFuncAttributeMaxDynamicSharedMemorySize, SMEM_DEC);
    cudaFuncSetAttribute(nconv_cat_mma<256, 256>, cudaFuncAttributeMaxDynamicSharedMemorySize, SMEM_DEC);
    cudaFuncSetAttribute(nconv_cat_mma<512, 512>, cudaFuncAttributeMaxDynamicSharedMemorySize, SMEM_DEC);

    const long HW = 512L * 512;

    wsum_kernel<<<7, 32>>>(w1, w2, w3, w4, w5, w6, w7, WS);
    prep_w<<<100, 256>>>(w2, PW2, 32, 25, 25600);
    prep_w<<<100, 256>>>(w3, PW3, 32, 25, 25600);
    prep_w<<<72, 256>>>(w4, PW4, 64, 9, 18432);
    prep_w<<<72, 256>>>(w5, PW5, 64, 9, 18432);
    prep_w<<<72, 256>>>(w6, PW6, 64, 9, 18432);

    // Encoder @512
    nconv_l1<512, 512><<<dim3(16, 64, 2), 256>>>(x, x + HW, 2 * HW, w1, b1, WS, P0x, P0c);
    nconv_mma<512, 512><<<dim3(16, 64, 2), 256, SMEM_ENC>>>(P0x, P0c, PW2, b2, WS + 32, P1x, P1c);
    nconv_mma<512, 512><<<dim3(16, 64, 2), 256, SMEM_ENC>>>(P1x, P1c, PW3, b3, WS + 64, X1, C1);

    // Down 1 @256
    pool_kernel<<<(int)((64L * 256 * 256 + 255) / 256), 256>>>(X1, C1, S0x, S0c, 256, 256);
    nconv_mma<256, 256><<<dim3(8, 32, 2), 256, SMEM_ENC>>>(S0x, S0c, PW2, b2, WS + 32, S1x, S1c);
    nconv_mma<256, 256><<<dim3(8, 32, 2), 256, SMEM_ENC>>>(S1x, S1c, PW3, b3, WS + 64, X2, C2);

    // Down 2 @128
    pool_kernel<<<(int)((64L * 128 * 128 + 255) / 256), 256>>>(X2, C2, S0x, S0c, 128, 128);
    nconv_mma<128, 128><<<dim3(4, 16, 2), 256, SMEM_ENC>>>(S0x, S0c, PW2, b2, WS + 32, X3, C3);

    // Down 3 @64
    pool_kernel<<<(int)((64L * 64 * 64 + 255) / 256), 256>>>(X3, C3, S1x, S1c, 64, 64);
    nconv_mma<64, 64><<<dim3(2, 8, 2), 256, SMEM_ENC>>>(S1x, S1c, PW2, b2, WS + 32, S0x, S0c);

    // Decoder
    nconv_cat_mma<128, 128><<<dim3(4, 16, 2), 256, SMEM_DEC>>>(
        X3, C3, 0, S0x, S0c, 1, PW4, b4, WS + 96, S1x, S1c);
    nconv_cat_mma<256, 256><<<dim3(8, 32, 2), 256, SMEM_DEC>>>(
        X2, C2, 0, S1x, S1c, 1, PW5, b5, WS + 128, S0x, S0c);
    nconv_cat_mma<512, 512><<<dim3(16, 64, 2), 256, SMEM_DEC>>>(
        S0x, S0c, 1, X1, C1, 0, PW6, b6, WS + 160, P0x, P0c);

    final1x1_kernel<<<2048, 256>>>(P0x, P0c, w7, b7, (float*)d_out);
}

// round 7
// speedup vs baseline: 5.0191x; 1.5614x over previous
#include <cuda_runtime.h>
#include <cuda_bf16.h>
#define EPSF 1e-20f

static constexpr long N512 = 2L * 32 * 512 * 512;
static constexpr long N256 = 2L * 32 * 256 * 256;
static constexpr long N128 = 2L * 32 * 128 * 128;
static constexpr long WP5 = 12800;  // floats holding 25600 bf16 (5x5 layer)
static constexpr long WP3 = 9216;   // floats holding 18432 bf16 (3x3 layer)
static constexpr long POOL_FLOATS =
    6 * N512 + 2 * N256 + 2 * N128 + 4 * N256 + 256 + 2 * WP5 + 3 * WP3;

__device__ __align__(16) float g_pool[POOL_FLOATS];

// ---------------- helpers ----------------
__device__ __forceinline__ unsigned long long pack2(float a, float b) {
    unsigned long long r;
    asm("mov.b64 %0, {%1, %2};" : "=l"(r) : "f"(a), "f"(b));
    return r;
}
__device__ __forceinline__ void unpack2(unsigned long long v, float& a, float& b) {
    asm("mov.b64 {%0, %1}, %2;" : "=f"(a), "=f"(b) : "l"(v));
}
__device__ __forceinline__ void ffma2(unsigned long long& acc, unsigned long long w2,
                                      unsigned long long m2) {
    asm("fma.rn.f32x2 %0, %1, %2, %0;" : "+l"(acc) : "l"(w2), "l"(m2));
}
__device__ __forceinline__ void cp_async4(unsigned dst, const float* src, bool valid) {
    int sz = valid ? 4 : 0;
    asm volatile("cp.async.ca.shared.global [%0], [%1], 4, %2;\n"
                 :: "r"(dst), "l"(src), "r"(sz));
}
__device__ __forceinline__ void cp_async16(unsigned dst, const float* src) {
    asm volatile("cp.async.ca.shared.global [%0], [%1], 16;\n" :: "r"(dst), "l"(src));
}
__device__ __forceinline__ void cp_commit() { asm volatile("cp.async.commit_group;\n"); }
template <int N>
__device__ __forceinline__ void cp_wait() {
    asm volatile("cp.async.wait_group %0;\n" :: "n"(N));
}
__device__ __forceinline__ unsigned bfp(float lo, float hi) {
    __nv_bfloat162 v = __floats2bfloat162_rn(lo, hi);
    return *reinterpret_cast<unsigned*>(&v);
}
__device__ __forceinline__ void ldsm4(unsigned& r0, unsigned& r1, unsigned& r2,
                                      unsigned& r3, unsigned addr) {
    asm volatile("ldmatrix.sync.aligned.m8n8.x4.shared.b16 {%0,%1,%2,%3}, [%4];"
                 : "=r"(r0), "=r"(r1), "=r"(r2), "=r"(r3) : "r"(addr));
}
__device__ __forceinline__ void mma16(float* d, unsigned a0, unsigned a1, unsigned a2,
                                      unsigned a3, unsigned b0, unsigned b1) {
    asm("mma.sync.aligned.m16n8k16.row.col.f32.bf16.bf16.f32 "
        "{%0,%1,%2,%3},{%4,%5,%6,%7},{%8,%9},{%0,%1,%2,%3};"
        : "+f"(d[0]), "+f"(d[1]), "+f"(d[2]), "+f"(d[3])
        : "r"(a0), "r"(a1), "r"(a2), "r"(a3), "r"(b0), "r"(b1));
}

// pack 16 raw fp32 ci -> bf16 [pix][16ci] with 16B-half swizzle
template <int NS>
__device__ __forceinline__ void pack_bf16(const float* rawx, const float* rawc,
                                          char* pxc, char* pc, int tid) {
    for (int p = tid; p < NS; p += 256) {
        const unsigned swp = (p >> 2) & 1;
#pragma unroll
        for (int h = 0; h < 2; h++) {
            float cv[8], xc[8];
#pragma unroll
            for (int j = 0; j < 8; j++) {
                const int ci = h * 8 + j;
                float c = rawc[ci * NS + p];
                cv[j] = c;
                xc[j] = rawx[ci * NS + p] * c;
            }
            uint4 vx, vc;
            vx.x = bfp(xc[0], xc[1]); vx.y = bfp(xc[2], xc[3]);
            vx.z = bfp(xc[4], xc[5]); vx.w = bfp(xc[6], xc[7]);
            vc.x = bfp(cv[0], cv[1]); vc.y = bfp(cv[2], cv[3]);
            vc.z = bfp(cv[4], cv[5]); vc.w = bfp(cv[6], cv[7]);
            const int off = p * 32 + ((h ^ swp) << 4);
            *reinterpret_cast<uint4*>(pxc + off) = vx;
            *reinterpret_cast<uint4*>(pc + off) = vc;
        }
    }
}

// bf16 MMA over all taps of one 16-ci chunk
template <int KS, int SW>
__device__ __forceinline__ void mma_taps_bf16(const unsigned* wq, unsigned pxc_s,
                                              unsigned pc_s, int wy, int lane,
                                              float (&accN)[2][4][4],
                                              float (&accD)[2][4][4]) {
    const int g = lane >> 2, t = lane & 3;
    const int hsw0 = (g >> 2) & 1;
    const int pxoff = ((lane >> 3) & 1) * 8 + (lane & 7);
    const int hbit = (lane >> 4) & 1;
#pragma unroll
    for (int ky = 0; ky < KS; ky++) {
#pragma unroll
        for (int kx = 0; kx < KS; kx++) {
            const int kk = ky * KS + kx;
            unsigned b0[4], b1[4];
#pragma unroll
            for (int nf = 0; nf < 4; nf++) {
                const unsigned* wrow = wq + kk * 256 + (nf * 8 + g) * 8;
                b0[nf] = wrow[hsw0 * 4 + t];
                b1[nf] = wrow[4 - hsw0 * 4 + t];
            }
#pragma unroll
            for (int mf = 0; mf < 2; mf++) {
                const int p = (wy + ky) * SW + mf * 16 + kx + pxoff;
                const unsigned off = p * 32 + ((((p >> 2) ^ hbit) & 1) << 4);
                unsigned ax0, ax1, ax2, ax3, ac0, ac1, ac2, ac3;
                ldsm4(ax0, ax1, ax2, ax3, pxc_s + off);
                ldsm4(ac0, ac1, ac2, ac3, pc_s + off);
#pragma unroll
                for (int nf = 0; nf < 4; nf++) {
                    mma16(accN[mf][nf], ax0, ax1, ax2, ax3, b0[nf], b1[nf]);
                    mma16(accD[mf][nf], ac0, ac1, ac2, ac3, b0[nf], b1[nf]);
                }
            }
        }
    }
}

__device__ __forceinline__ void epi(float (&aN)[2][4][4], float (&aD)[2][4][4],
                                    const float* bias, const float* winv,
                                    float* xout, float* cout, long PLANE, int WW,
                                    int bz, int y, int bx, int g, int t) {
#pragma unroll
    for (int mf = 0; mf < 2; mf++)
#pragma unroll
        for (int nf = 0; nf < 4; nf++) {
            const int co = nf * 8 + 2 * t;
            const int px = bx + mf * 16 + g;
            const long base = ((long)bz * 32 + co) * PLANE + (long)y * WW;
            float* n = aN[mf][nf];
            float* d = aD[mf][nf];
            xout[base + px]             = n[0] / (d[0] + EPSF) + bias[co];
            xout[base + PLANE + px]     = n[1] / (d[1] + EPSF) + bias[co + 1];
            xout[base + px + 8]         = n[2] / (d[2] + EPSF) + bias[co];
            xout[base + PLANE + px + 8] = n[3] / (d[3] + EPSF) + bias[co + 1];
            cout[base + px]             = d[0] * winv[co];
            cout[base + PLANE + px]     = d[1] * winv[co + 1];
            cout[base + px + 8]         = d[2] * winv[co];
            cout[base + PLANE + px + 8] = d[3] * winv[co + 1];
        }
}

// ---------------- small kernels ----------------
__global__ void wsum_kernel(const float* __restrict__ w1, const float* __restrict__ w2,
                            const float* __restrict__ w3, const float* __restrict__ w4,
                            const float* __restrict__ w5, const float* __restrict__ w6,
                            const float* __restrict__ w7, float* __restrict__ inv) {
    int l = blockIdx.x, co = threadIdx.x;
    const float* w; int n; int nco = 32;
    if      (l == 0) { w = w1; n = 1 * 25; }
    else if (l == 1) { w = w2; n = 32 * 25; }
    else if (l == 2) { w = w3; n = 32 * 25; }
    else if (l == 3) { w = w4; n = 64 * 9; }
    else if (l == 4) { w = w5; n = 64 * 9; }
    else if (l == 5) { w = w6; n = 64 * 9; }
    else             { w = w7; n = 32;  nco = 1; }
    if (co >= nco) return;
    float s = 0.f;
    for (int i = 0; i < n; i++) s += w[co * n + i];
    inv[l * 32 + co] = 1.0f / s;
}

// weight prep: OIHW -> bf16 [chunk][kk][co32][swizzled 16ci]
__global__ void prep_w_bf16(const float* __restrict__ w, __nv_bfloat16* __restrict__ dst,
                            int CIN, int KK, int total) {
    int i = blockIdx.x * 256 + threadIdx.x;
    if (i >= total) return;
    int cilo = i & 7;
    int hsw = (i >> 3) & 1;
    int co = (i >> 4) & 31;
    int r = i >> 9;
    int kk = r % KK, chunk = r / KK;
    int h = hsw ^ ((co >> 2) & 1);
    int ci = chunk * 16 + h * 8 + cilo;
    dst[i] = __float2bfloat16(w[((long)co * CIN + ci) * KK + kk]);
}

__global__ void pool_kernel(const float* __restrict__ xin, const float* __restrict__ cin,
                            float* __restrict__ xout, float* __restrict__ cout,
                            int Ho, int Wo) {
    long i = (long)blockIdx.x * blockDim.x + threadIdx.x;
    long total = 64L * Ho * Wo;
    if (i >= total) return;
    int xo = (int)(i % Wo);
    long t = i / Wo;
    int yo = (int)(t % Ho);
    long bc = t / Ho;
    const int Wi = 2 * Wo;
    long ib = bc * 4L * Ho * Wo + (long)(2 * yo) * Wi + 2 * xo;
    float c00 = cin[ib], c01 = cin[ib + 1], c10 = cin[ib + Wi], c11 = cin[ib + Wi + 1];
    float best = c00; int bi = 0;
    if (c01 > best) { best = c01; bi = 1; }
    if (c10 > best) { best = c10; bi = 2; }
    if (c11 > best) { best = c11; bi = 3; }
    long off = (long)(bi >> 1) * Wi + (bi & 1);
    xout[i] = xin[ib + off];
    cout[i] = best * 0.25f;
}

__global__ void final1x1_kernel(const float* __restrict__ xin, const float* __restrict__ cin,
                                const float* __restrict__ w7, const float* __restrict__ b7,
                                float* __restrict__ out) {
    constexpr long HW = 512L * 512L;
    long i = (long)blockIdx.x * blockDim.x + threadIdx.x;
    if (i >= 2 * HW) return;
    int b = (int)(i / HW);
    long p = i - (long)b * HW;
    const float* xb = xin + (long)b * 32 * HW + p;
    const float* cb = cin + (long)b * 32 * HW + p;
    float n = 0.f, d = 0.f;
#pragma unroll
    for (int ci = 0; ci < 32; ci++) {
        float wv = __ldg(w7 + ci);
        float cv = __ldg(cb + (long)ci * HW);
        float xv = __ldg(xb + (long)ci * HW);
        n += wv * xv * cv;
        d += wv * cv;
    }
    out[i] = n / (d + EPSF) + __ldg(b7);
}

// layer1 scalar nconv: 5x5, CIN=1 -> 32
template <int HH, int WW>
__global__ __launch_bounds__(256)
void nconv_l1(const float* __restrict__ xin, const float* __restrict__ cin, long bstride,
              const float* __restrict__ w, const float* __restrict__ bias,
              const float* __restrict__ winv,
              float* __restrict__ xout, float* __restrict__ cout) {
    constexpr int PAD = 2, SW = 36, SH = 12, NS = SW * SH;
    constexpr long PLANE = (long)HH * WW;
    __shared__ __align__(16) float ws[25][32];
    __shared__ float cs[NS], xcs[NS];
    const int tid = threadIdx.x, tx = tid & 31, ty = tid >> 5;
    const int bx = blockIdx.x * 32, by = blockIdx.y * 8, b = blockIdx.z;
    for (int i = tid; i < 800; i += 256) ws[i >> 5][i & 31] = w[(i & 31) * 25 + (i >> 5)];
    const float* xp = xin + (long)b * bstride;
    const float* cp = cin + (long)b * bstride;
    for (int i = tid; i < NS; i += 256) {
        int r = i / SW, c = i - r * SW;
        int gy = by + r - PAD, gx = bx + c - PAD;
        float cv = 0.f, xv = 0.f;
        if ((unsigned)gy < (unsigned)HH && (unsigned)gx < (unsigned)WW) {
            long gg = (long)gy * WW + gx;
            cv = cp[gg]; xv = xp[gg];
        }
        cs[i] = cv; xcs[i] = xv * cv;
    }
    __syncthreads();
    unsigned long long accN[16], accD[16];
#pragma unroll
    for (int q = 0; q < 16; q++) { accN[q] = 0ULL; accD[q] = 0ULL; }
#pragma unroll
    for (int ky = 0; ky < 5; ky++)
#pragma unroll
        for (int kx = 0; kx < 5; kx++) {
            float cv = cs[(ty + ky) * SW + tx + kx];
            float xc = xcs[(ty + ky) * SW + tx + kx];
            unsigned long long c2 = pack2(cv, cv), x2 = pack2(xc, xc);
            const float* wr = &ws[ky * 5 + kx][0];
#pragma unroll
            for (int q = 0; q < 8; q++) {
                ulonglong2 wv = *reinterpret_cast<const ulonglong2*>(wr + q * 4);
                ffma2(accN[2 * q], wv.x, x2);     ffma2(accD[2 * q], wv.x, c2);
                ffma2(accN[2 * q + 1], wv.y, x2); ffma2(accD[2 * q + 1], wv.y, c2);
            }
        }
    const long pix = (long)(by + ty) * WW + bx + tx;
#pragma unroll
    for (int q = 0; q < 16; q++) {
        float n0, n1, d0, d1;
        unpack2(accN[q], n0, n1); unpack2(accD[q], d0, d1);
        const int co = 2 * q;
        const long o = ((long)b * 32 + co) * PLANE + pix;
        xout[o]         = n0 / (d0 + EPSF) + bias[co];
        xout[o + PLANE] = n1 / (d1 + EPSF) + bias[co + 1];
        cout[o]         = d0 * winv[co];
        cout[o + PLANE] = d1 * winv[co + 1];
    }
}

// ---------------- bf16 tensor-core encoder nconv: 5x5, 32->32 ----------------
template <int HH, int WW>
__global__ __launch_bounds__(256, 2)
void nconv_mma(const float* __restrict__ xin, const float* __restrict__ cin,
               const unsigned short* __restrict__ wp, const float* __restrict__ bias,
               const float* __restrict__ winv,
               float* __restrict__ xout, float* __restrict__ cout) {
    constexpr int KS = 5, PAD = 2, SW = 36, SH = 12, NS = SH * SW;
    constexpr int NCH = 2, WCHB = 25 * 512 * 2;  // bytes per chunk
    constexpr long PLANE = (long)HH * WW;
    extern __shared__ float dsm[];
    float* rawx = dsm;                       // 16*NS f32
    float* rawc = rawx + 16 * NS;
    char* pxc = (char*)(rawc + 16 * NS);     // NS*32 B bf16
    char* pc  = pxc + NS * 32;
    char* wsb = pc + NS * 32;                // WCHB (single buffer)

    const int tid = threadIdx.x, wy = tid >> 5, lane = tid & 31;
    const int g = lane >> 2, t = lane & 3;
    const int bx = blockIdx.x * 32, by = blockIdx.y * 8, bz = blockIdx.z;

    const int p0 = tid, p1 = tid + 256;
    long g0 = 0, g1 = 0; bool v0 = false, v1 = false;
    {
        int r = p0 / SW, c = p0 - r * SW;
        int gy = by + r - PAD, gx = bx + c - PAD;
        v0 = (unsigned)gy < (unsigned)HH && (unsigned)gx < (unsigned)WW;
        g0 = v0 ? (long)gy * WW + gx : 0;
    }
    if (p1 < NS) {
        int r = p1 / SW, c = p1 - r * SW;
        int gy = by + r - PAD, gx = bx + c - PAD;
        v1 = (unsigned)gy < (unsigned)HH && (unsigned)gx < (unsigned)WW;
        g1 = v1 ? (long)gy * WW + gx : 0;
    }
    const float* xb = xin + (long)bz * 32 * PLANE;
    const float* cb = cin + (long)bz * 32 * PLANE;
    const unsigned rx_s = (unsigned)__cvta_generic_to_shared(rawx);
    const unsigned rc_s = (unsigned)__cvta_generic_to_shared(rawc);
    const unsigned ws_s = (unsigned)__cvta_generic_to_shared(wsb);
    const unsigned pxc_s = (unsigned)__cvta_generic_to_shared(pxc);
    const unsigned pc_s  = (unsigned)__cvta_generic_to_shared(pc);

    auto stage_raw = [&](int ch) {
#pragma unroll
        for (int ci = 0; ci < 16; ci++) {
            const float* xp = xb + (long)(ch * 16 + ci) * PLANE;
            const float* cp = cb + (long)(ch * 16 + ci) * PLANE;
            cp_async4(rx_s + (ci * NS + p0) * 4, xp + g0, v0);
            cp_async4(rc_s + (ci * NS + p0) * 4, cp + g0, v0);
            if (p1 < NS) {
                cp_async4(rx_s + (ci * NS + p1) * 4, xp + g1, v1);
                cp_async4(rc_s + (ci * NS + p1) * 4, cp + g1, v1);
            }
        }
    };
    auto stage_w = [&](int ch) {
        const float* src = (const float*)((const char*)wp + ch * WCHB);
        for (int i = tid; i < WCHB / 16; i += 256) cp_async16(ws_s + i * 16, src + i * 4);
    };

    stage_raw(0); stage_w(0); cp_commit();

    float accN[2][4][4] = {}, accD[2][4][4] = {};
    const unsigned* wq = reinterpret_cast<const unsigned*>(wsb);

#pragma unroll 1
    for (int ch = 0; ch < NCH; ch++) {
        cp_wait<0>();
        __syncthreads();
        if (ch > 0) { stage_w(ch); cp_commit(); }
        pack_bf16<NS>(rawx, rawc, pxc, pc, tid);
        cp_wait<0>();
        __syncthreads();
        if (ch + 1 < NCH) { stage_raw(ch + 1); cp_commit(); }
        mma_taps_bf16<KS, SW>(wq, pxc_s, pc_s, wy, lane, accN, accD);
    }
    epi(accN, accD, bias, winv, xout, cout, PLANE, WW, bz, by + wy, bx, g, t);
}

// ------- bf16 tensor-core decoder nconv: 3x3, 64->32, cat + up2 -------
template <int HH, int WW>
__global__ __launch_bounds__(256, 2)
void nconv_cat_mma(const float* __restrict__ x0p, const float* __restrict__ c0p, int half0,
                   const float* __restrict__ x1p, const float* __restrict__ c1p, int half1,
                   const unsigned short* __restrict__ wp, const float* __restrict__ bias,
                   const float* __restrict__ winv,
                   float* __restrict__ xout, float* __restrict__ cout) {
    constexpr int KS = 3, PAD = 1, SW = 34, SH = 10, NS = SH * SW;
    constexpr int NCH = 4, WCHB = 9 * 512 * 2;
    constexpr int W2 = WW / 2;
    constexpr long PLANE = (long)HH * WW;
    extern __shared__ float dsm[];
    float* rawx = dsm;
    float* rawc = rawx + 16 * NS;
    char* pxc = (char*)(rawc + 16 * NS);
    char* pc  = pxc + NS * 32;
    char* wsb = pc + NS * 32;                // 2 * WCHB

    const int tid = threadIdx.x, wy = tid >> 5, lane = tid & 31;
    const int g = lane >> 2, t = lane & 3;
    const int bx = blockIdx.x * 32, by = blockIdx.y * 8, bz = blockIdx.z;

    const int p0 = tid, p1 = tid + 256;
    long g0F = 0, g0H = 0, g1F = 0, g1H = 0; bool v0 = false, v1 = false;
    {
        int r = p0 / SW, c = p0 - r * SW;
        int gy = by + r - PAD, gx = bx + c - PAD;
        v0 = (unsigned)gy < (unsigned)HH && (unsigned)gx < (unsigned)WW;
        g0F = v0 ? (long)gy * WW + gx : 0;
        g0H = v0 ? (long)(gy >> 1) * W2 + (gx >> 1) : 0;
    }
    if (p1 < NS) {
        int r = p1 / SW, c = p1 - r * SW;
        int gy = by + r - PAD, gx = bx + c - PAD;
        v1 = (unsigned)gy < (unsigned)HH && (unsigned)gx < (unsigned)WW;
        g1F = v1 ? (long)gy * WW + gx : 0;
        g1H = v1 ? (long)(gy >> 1) * W2 + (gx >> 1) : 0;
    }
    const unsigned rx_s = (unsigned)__cvta_generic_to_shared(rawx);
    const unsigned rc_s = (unsigned)__cvta_generic_to_shared(rawc);
    const unsigned ws_s = (unsigned)__cvta_generic_to_shared(wsb);
    const unsigned pxc_s = (unsigned)__cvta_generic_to_shared(pxc);
    const unsigned pc_s  = (unsigned)__cvta_generic_to_shared(pc);

    auto stage_raw = [&](int ch) {
        const int grp = ch >> 1;
        const float* xs = grp ? x1p : x0p;
        const float* cc = grp ? c1p : c0p;
        const int half = grp ? half1 : half0;
        const long plane = half ? (long)(HH / 2) * W2 : PLANE;
        const long o0 = half ? g0H : g0F;
        const long o1 = half ? g1H : g1F;
        const int cbase = (ch & 1) * 16;
#pragma unroll
        for (int ci = 0; ci < 16; ci++) {
            const float* xp = xs + ((long)bz * 32 + cbase + ci) * plane;
            const float* cp = cc + ((long)bz * 32 + cbase + ci) * plane;
            cp_async4(rx_s + (ci * NS + p0) * 4, xp + o0, v0);
            cp_async4(rc_s + (ci * NS + p0) * 4, cp + o0, v0);
            if (p1 < NS) {
                cp_async4(rx_s + (ci * NS + p1) * 4, xp + o1, v1);
                cp_async4(rc_s + (ci * NS + p1) * 4, cp + o1, v1);
            }
        }
    };
    auto stage_w = [&](int ch) {
        const float* src = (const float*)((const char*)wp + ch * WCHB);
        const unsigned dst = ws_s + (ch & 1) * WCHB;
        for (int i = tid; i < WCHB / 16; i += 256) cp_async16(dst + i * 16, src + i * 4);
    };

    stage_raw(0); stage_w(0); cp_commit();

    float accN[2][4][4] = {}, accD[2][4][4] = {};

#pragma unroll 1
    for (int ch = 0; ch < NCH; ch++) {
        cp_wait<0>();
        __syncthreads();
        pack_bf16<NS>(rawx, rawc, pxc, pc, tid);
        __syncthreads();
        if (ch + 1 < NCH) { stage_raw(ch + 1); stage_w(ch + 1); cp_commit(); }
        const unsigned* wq = reinterpret_cast<const unsigned*>(wsb + (ch & 1) * WCHB);
        mma_taps_bf16<KS, SW>(wq, pxc_s, pc_s, wy, lane, accN, accD);
    }
    epi(accN, accD, bias, winv, xout, cout, PLANE, WW, bz, by + wy, bx, g, t);
}

// ---------------- launch ----------------
static constexpr int SMEM_ENC = 16 * 432 * 4 * 2 + 432 * 32 * 2 + 25 * 512 * 2;      // 108544
static constexpr int SMEM_DEC = 16 * 340 * 4 * 2 + 340 * 32 * 2 + 2 * 9 * 512 * 2;   // 83712

extern "C" void kernel_launch(void* const* d_in, const int* in_sizes, int n_in,
                              void* d_out, int out_size) {
    const float* x  = (const float*)d_in[0];
    const float* w1 = (const float*)d_in[1];  const float* b1 = (const float*)d_in[2];
    const float* w2 = (const float*)d_in[3];  const float* b2 = (const float*)d_in[4];
    const float* w3 = (const float*)d_in[5];  const float* b3 = (const float*)d_in[6];
    const float* w4 = (const float*)d_in[7];  const float* b4 = (const float*)d_in[8];
    const float* w5 = (const float*)d_in[9];  const float* b5 = (const float*)d_in[10];
    const float* w6 = (const float*)d_in[11]; const float* b6 = (const float*)d_in[12];
    const float* w7 = (const float*)d_in[13]; const float* b7 = (const float*)d_in[14];

    float* pool = nullptr;
    cudaGetSymbolAddress((void**)&pool, g_pool);

    float* P0x = pool;
    float* P0c = pool + N512;
    float* P1x = pool + 2 * N512;
    float* P1c = pool + 3 * N512;
    float* X1  = pool + 4 * N512;
    float* C1  = pool + 5 * N512;
    float* X2  = pool + 6 * N512;
    float* C2  = X2 + N256;
    float* X3  = C2 + N256;
    float* C3  = X3 + N128;
    float* S0x = C3 + N128;
    float* S0c = S0x + N256;
    float* S1x = S0c + N256;
    float* S1c = S1x + N256;
    float* WS  = S1c + N256;
    __nv_bfloat16* PW2 = (__nv_bfloat16*)(WS + 256);
    __nv_bfloat16* PW3 = (__nv_bfloat16*)(WS + 256 + WP5);
    __nv_bfloat16* PW4 = (__nv_bfloat16*)(WS + 256 + 2 * WP5);
    __nv_bfloat16* PW5 = (__nv_bfloat16*)(WS + 256 + 2 * WP5 + WP3);
    __nv_bfloat16* PW6 = (__nv_bfloat16*)(WS + 256 + 2 * WP5 + 2 * WP3);

    cudaFuncSetAttribute(nconv_mma<512, 512>, cudaFuncAttributeMaxDynamicSharedMemorySize, SMEM_ENC);
    cudaFuncSetAttribute(nconv_mma<256, 256>, cudaFuncAttributeMaxDynamicSharedMemorySize, SMEM_ENC);
    cudaFuncSetAttribute(nconv_mma<128, 128>, cudaFuncAttributeMaxDynamicSharedMemorySize, SMEM_ENC);
    cudaFuncSetAttribute(nconv_mma<64, 64>,   cudaFuncAttributeMaxDynamicSharedMemorySize, SMEM_ENC);
    cudaFuncSetAttribute(nconv_cat_mma<128, 128>, cudaFuncAttributeMaxDynamicSharedMemorySize, SMEM_DEC);
    cudaFuncSetAttribute(nconv_cat_mma<256, 256>, cudaFuncAttributeMaxDynamicSharedMemorySize, SMEM_DEC);
    cudaFuncSetAttribute(nconv_cat_mma<512, 512>, cudaFuncAttributeMaxDynamicSharedMemorySize, SMEM_DEC);

    const long HW = 512L * 512;

    wsum_kernel<<<7, 32>>>(w1, w2, w3, w4, w5, w6, w7, WS);
    prep_w_bf16<<<100, 256>>>(w2, PW2, 32, 25, 25600);
    prep_w_bf16<<<100, 256>>>(w3, PW3, 32, 25, 25600);
    prep_w_bf16<<<72, 256>>>(w4, PW4, 64, 9, 18432);
    prep_w_bf16<<<72, 256>>>(w5, PW5, 64, 9, 18432);
    prep_w_bf16<<<72, 256>>>(w6, PW6, 64, 9, 18432);

    // Encoder @512
    nconv_l1<512, 512><<<dim3(16, 64, 2), 256>>>(x, x + HW, 2 * HW, w1, b1, WS, P0x, P0c);
    nconv_mma<512, 512><<<dim3(16, 64, 2), 256, SMEM_ENC>>>(
        P0x, P0c, (const unsigned short*)PW2, b2, WS + 32, P1x, P1c);
    nconv_mma<512, 512><<<dim3(16, 64, 2), 256, SMEM_ENC>>>(
        P1x, P1c, (const unsigned short*)PW3, b3, WS + 64, X1, C1);

    // Down 1 @256
    pool_kernel<<<(int)((64L * 256 * 256 + 255) / 256), 256>>>(X1, C1, S0x, S0c, 256, 256);
    nconv_mma<256, 256><<<dim3(8, 32, 2), 256, SMEM_ENC>>>(
        S0x, S0c, (const unsigned short*)PW2, b2, WS + 32, S1x, S1c);
    nconv_mma<256, 256><<<dim3(8, 32, 2), 256, SMEM_ENC>>>(
        S1x, S1c, (const unsigned short*)PW3, b3, WS + 64, X2, C2);

    // Down 2 @128
    pool_kernel<<<(int)((64L * 128 * 128 + 255) / 256), 256>>>(X2, C2, S0x, S0c, 128, 128);
    nconv_mma<128, 128><<<dim3(4, 16, 2), 256, SMEM_ENC>>>(
        S0x, S0c, (const unsigned short*)PW2, b2, WS + 32, X3, C3);

    // Down 3 @64
    pool_kernel<<<(int)((64L * 64 * 64 + 255) / 256), 256>>>(X3, C3, S1x, S1c, 64, 64);
    nconv_mma<64, 64><<<dim3(2, 8, 2), 256, SMEM_ENC>>>(
        S1x, S1c, (const unsigned short*)PW2, b2, WS + 32, S0x, S0c);

    // Decoder
    nconv_cat_mma<128, 128><<<dim3(4, 16, 2), 256, SMEM_DEC>>>(
        X3, C3, 0, S0x, S0c, 1, (const unsigned short*)PW4, b4, WS + 96, S1x, S1c);
    nconv_cat_mma<256, 256><<<dim3(8, 32, 2), 256, SMEM_DEC>>>(
        X2, C2, 0, S1x, S1c, 1, (const unsigned short*)PW5, b5, WS + 128, S0x, S0c);
    nconv_cat_mma<512, 512><<<dim3(16, 64, 2), 256, SMEM_DEC>>>(
        S0x, S0c, 1, X1, C1, 0, (const unsigned short*)PW6, b6, WS + 160, P0x, P0c);

    final1x1_kernel<<<2048, 256>>>(P0x, P0c, w7, b7, (float*)d_out);
}

// round 11
// speedup vs baseline: 7.0033x; 1.3953x over previous
#include <cuda_runtime.h>
#include <cuda_bf16.h>
#define EPSF 1e-20f

static constexpr long N512 = 2L * 32 * 512 * 512;
static constexpr long N256 = N512 / 4;
static constexpr long N128 = N512 / 16;
static constexpr long N64  = N512 / 64;
static constexpr long POOL_FLOATS =
    3 * N512 + 4 * N256 + 3 * N128 + 2 * N64 + 4096 + 2 * 12800 + 3 * 9216;

__device__ __align__(16) float g_pool[POOL_FLOATS];

// ---------------- helpers ----------------
__device__ __forceinline__ unsigned long long pack2(float a, float b) {
    unsigned long long r;
    asm("mov.b64 %0, {%1, %2};" : "=l"(r) : "f"(a), "f"(b));
    return r;
}
__device__ __forceinline__ void unpack2(unsigned long long v, float& a, float& b) {
    asm("mov.b64 {%0, %1}, %2;" : "=f"(a), "=f"(b) : "l"(v));
}
__device__ __forceinline__ void ffma2(unsigned long long& acc, unsigned long long w2,
                                      unsigned long long m2) {
    asm("fma.rn.f32x2 %0, %1, %2, %0;" : "+l"(acc) : "l"(w2), "l"(m2));
}
__device__ __forceinline__ void cp_async16(unsigned dst, const void* src) {
    asm volatile("cp.async.cg.shared.global [%0], [%1], 16;\n" :: "r"(dst), "l"(src));
}
__device__ __forceinline__ void cp_async16z(unsigned dst, const void* src, bool v) {
    int sz = v ? 16 : 0;
    asm volatile("cp.async.cg.shared.global [%0], [%1], 16, %2;\n"
                 :: "r"(dst), "l"(src), "r"(sz));
}
__device__ __forceinline__ void cp_commit() { asm volatile("cp.async.commit_group;\n"); }
template <int N>
__device__ __forceinline__ void cp_wait() {
    asm volatile("cp.async.wait_group %0;\n" :: "n"(N));
}
__device__ __forceinline__ unsigned bfp(float lo, float hi) {
    __nv_bfloat162 v = __floats2bfloat162_rn(lo, hi);
    return *reinterpret_cast<unsigned*>(&v);
}
__device__ __forceinline__ void ldsm4(unsigned& r0, unsigned& r1, unsigned& r2,
                                      unsigned& r3, unsigned addr) {
    asm volatile("ldmatrix.sync.aligned.m8n8.x4.shared.b16 {%0,%1,%2,%3}, [%4];"
                 : "=r"(r0), "=r"(r1), "=r"(r2), "=r"(r3) : "r"(addr));
}
__device__ __forceinline__ void mma16(float* d, unsigned a0, unsigned a1, unsigned a2,
                                      unsigned a3, unsigned b0, unsigned b1) {
    asm("mma.sync.aligned.m16n8k16.row.col.f32.bf16.bf16.f32 "
        "{%0,%1,%2,%3},{%4,%5,%6,%7},{%8,%9},{%0,%1,%2,%3};"
        : "+f"(d[0]), "+f"(d[1]), "+f"(d[2]), "+f"(d[3])
        : "r"(a0), "r"(a1), "r"(a2), "r"(a3), "r"(b0), "r"(b1));
}

// bf16 MMA over all taps of one 16-ci chunk (layout identical to round-7)
template <int KS, int SW>
__device__ __forceinline__ void mma_taps_bf16(const unsigned* wq, unsigned pxc_s,
                                              unsigned pc_s, int wy, int lane,
                                              float (&accN)[2][4][4],
                                              float (&accD)[2][4][4]) {
    const int g = lane >> 2, t = lane & 3;
    const int hsw0 = (g >> 2) & 1;
    const int pxoff = ((lane >> 3) & 1) * 8 + (lane & 7);
    const int hbit = (lane >> 4) & 1;
#pragma unroll
    for (int ky = 0; ky < KS; ky++) {
#pragma unroll
        for (int kx = 0; kx < KS; kx++) {
            const int kk = ky * KS + kx;
            unsigned b0[4], b1[4];
#pragma unroll
            for (int nf = 0; nf < 4; nf++) {
                const unsigned* wrow = wq + kk * 256 + (nf * 8 + g) * 8;
                b0[nf] = wrow[hsw0 * 4 + t];
                b1[nf] = wrow[4 - hsw0 * 4 + t];
            }
#pragma unroll
            for (int mf = 0; mf < 2; mf++) {
                const int p = (wy + ky) * SW + mf * 16 + kx + pxoff;
                const unsigned off = p * 32 + ((((p >> 2) ^ hbit) & 1) << 4);
                unsigned ax0, ax1, ax2, ax3, ac0, ac1, ac2, ac3;
                ldsm4(ax0, ax1, ax2, ax3, pxc_s + off);
                ldsm4(ac0, ac1, ac2, ac3, pc_s + off);
#pragma unroll
                for (int nf = 0; nf < 4; nf++) {
                    mma16(accN[mf][nf], ax0, ax1, ax2, ax3, b0[nf], b1[nf]);
                    mma16(accD[mf][nf], ac0, ac1, ac2, ac3, b0[nf], b1[nf]);
                }
            }
        }
    }
}

// epilogue -> packed bf16 [pix][64B xc | 64B c]
__device__ __forceinline__ void epi_packed(float (&aN)[2][4][4], float (&aD)[2][4][4],
                                           const float* bias, const float* winv,
                                           char* out, long PLANE, int WW,
                                           int bz, int y, int bx, int g, int t) {
    char* ob = out + ((long)bz * PLANE + (long)y * WW) * 128;
#pragma unroll
    for (int mf = 0; mf < 2; mf++) {
        const int px0 = bx + mf * 16 + g;
#pragma unroll
        for (int nf = 0; nf < 4; nf++) {
            const int co = nf * 8 + 2 * t;
            const float bi0 = bias[co], bi1 = bias[co + 1];
            const float wv0 = winv[co], wv1 = winv[co + 1];
            float* n = aN[mf][nf];
            float* d = aD[mf][nf];
            float x00 = n[0] / (d[0] + EPSF) + bi0, c00 = d[0] * wv0;
            float x01 = n[1] / (d[1] + EPSF) + bi1, c01 = d[1] * wv1;
            float x10 = n[2] / (d[2] + EPSF) + bi0, c10 = d[2] * wv0;
            float x11 = n[3] / (d[3] + EPSF) + bi1, c11 = d[3] * wv1;
            const int wo = nf * 16 + t * 4;
            *(unsigned*)(ob + (long)px0 * 128 + wo)            = bfp(x00 * c00, x01 * c01);
            *(unsigned*)(ob + (long)px0 * 128 + 64 + wo)       = bfp(c00, c01);
            *(unsigned*)(ob + (long)(px0 + 8) * 128 + wo)      = bfp(x10 * c10, x11 * c11);
            *(unsigned*)(ob + (long)(px0 + 8) * 128 + 64 + wo) = bfp(c10, c11);
        }
    }
}

// ---------------- small kernels ----------------
__global__ void wsum_kernel(const float* __restrict__ w1, const float* __restrict__ w2,
                            const float* __restrict__ w3, const float* __restrict__ w4,
                            const float* __restrict__ w5, const float* __restrict__ w6,
                            const float* __restrict__ w7, float* __restrict__ inv) {
    int l = blockIdx.x, co = threadIdx.x;
    const float* w; int n; int nco = 32;
    if      (l == 0) { w = w1; n = 1 * 25; }
    else if (l == 1) { w = w2; n = 32 * 25; }
    else if (l == 2) { w = w3; n = 32 * 25; }
    else if (l == 3) { w = w4; n = 64 * 9; }
    else if (l == 4) { w = w5; n = 64 * 9; }
    else if (l == 5) { w = w6; n = 64 * 9; }
    else             { w = w7; n = 32;  nco = 1; }
    if (co >= nco) return;
    float s = 0.f;
    for (int i = 0; i < n; i++) s += w[co * n + i];
    inv[l * 32 + co] = 1.0f / s;
}

// weight prep: OIHW -> bf16 [chunk][kk][co32][swizzled 16ci]
__global__ void prep_w_bf16(const float* __restrict__ w, __nv_bfloat16* __restrict__ dst,
                            int CIN, int KK, int total) {
    int i = blockIdx.x * 256 + threadIdx.x;
    if (i >= total) return;
    int cilo = i & 7;
    int hsw = (i >> 3) & 1;
    int co = (i >> 4) & 31;
    int r = i >> 9;
    int kk = r % KK, chunk = r / KK;
    int h = hsw ^ ((co >> 2) & 1);
    int ci = chunk * 16 + h * 8 + cilo;
    dst[i] = __float2bfloat16(w[((long)co * CIN + ci) * KK + kk]);
}

// pool on packed tensors: per-channel 2x2 argmax of c, gather xc, /4
__global__ void pool_p(const char* __restrict__ in, char* __restrict__ out,
                       int Ho, int Wo) {
    int idx = blockIdx.x * 256 + threadIdx.x;
    int total = 2 * Ho * Wo * 2;
    if (idx >= total) return;
    int chunk = idx & 1;
    int r = idx >> 1;
    int xo = r % Wo; r /= Wo;
    int yo = r % Ho; int b = r / Ho;
    int Wi = Wo * 2;
    const char* ib = in + ((long)b * 4 * Ho * Wo + (long)(2 * yo) * Wi + 2 * xo) * 128;
    long poff[4] = {0, 128, (long)Wi * 128, (long)Wi * 128 + 128};
    unsigned cw[4][8], xw[4][8];
#pragma unroll
    for (int k = 0; k < 4; k++) {
        uint4 a = *(const uint4*)(ib + poff[k] + 64 + chunk * 32);
        uint4 bq = *(const uint4*)(ib + poff[k] + 80 + chunk * 32);
        cw[k][0] = a.x; cw[k][1] = a.y; cw[k][2] = a.z; cw[k][3] = a.w;
        cw[k][4] = bq.x; cw[k][5] = bq.y; cw[k][6] = bq.z; cw[k][7] = bq.w;
        a = *(const uint4*)(ib + poff[k] + chunk * 32);
        bq = *(const uint4*)(ib + poff[k] + 16 + chunk * 32);
        xw[k][0] = a.x; xw[k][1] = a.y; xw[k][2] = a.z; xw[k][3] = a.w;
        xw[k][4] = bq.x; xw[k][5] = bq.y; xw[k][6] = bq.z; xw[k][7] = bq.w;
    }
    unsigned oc[8], ox[8];
#pragma unroll
    for (int w = 0; w < 8; w++) {
        float bl = -1e30f, bh = -1e30f; int kl = 0, kh = 0;
#pragma unroll
        for (int k = 0; k < 4; k++) {
            __nv_bfloat162 v = *reinterpret_cast<__nv_bfloat162*>(&cw[k][w]);
            float2 f = __bfloat1622float2(v);
            if (f.x > bl) { bl = f.x; kl = k; }
            if (f.y > bh) { bh = f.y; kh = k; }
        }
        oc[w] = bfp(bl * 0.25f, bh * 0.25f);
        __nv_bfloat162 xl = *reinterpret_cast<__nv_bfloat162*>(&xw[kl][w]);
        __nv_bfloat162 xh = *reinterpret_cast<__nv_bfloat162*>(&xw[kh][w]);
        ox[w] = bfp(__low2float(xl) * 0.25f, __high2float(xh) * 0.25f);
    }
    char* ob = out + ((long)b * Ho * Wo + (long)yo * Wo + xo) * 128;
    *(uint4*)(ob + chunk * 32)      = make_uint4(ox[0], ox[1], ox[2], ox[3]);
    *(uint4*)(ob + 16 + chunk * 32) = make_uint4(ox[4], ox[5], ox[6], ox[7]);
    *(uint4*)(ob + 64 + chunk * 32) = make_uint4(oc[0], oc[1], oc[2], oc[3]);
    *(uint4*)(ob + 80 + chunk * 32) = make_uint4(oc[4], oc[5], oc[6], oc[7]);
}

// layer1 scalar nconv: 5x5, CIN=1 -> 32, packed bf16 output
template <int HH, int WW>
__global__ __launch_bounds__(256)
void nconv_l1(const float* __restrict__ xin, const float* __restrict__ cin, long bstride,
              const float* __restrict__ w, const float* __restrict__ bias,
              const float* __restrict__ winv, char* __restrict__ out) {
    constexpr int PAD = 2, SW = 36, SH = 12, NS = SW * SH;
    constexpr long PLANE = (long)HH * WW;
    __shared__ __align__(16) float ws[25][32];
    __shared__ float cs[NS], xcs[NS];
    const int tid = threadIdx.x, tx = tid & 31, ty = tid >> 5;
    const int bx = blockIdx.x * 32, by = blockIdx.y * 8, b = blockIdx.z;
    for (int i = tid; i < 800; i += 256) ws[i >> 5][i & 31] = w[(i & 31) * 25 + (i >> 5)];
    const float* xp = xin + (long)b * bstride;
    const float* cp = cin + (long)b * bstride;
    for (int i = tid; i < NS; i += 256) {
        int r = i / SW, c = i - r * SW;
        int gy = by + r - PAD, gx = bx + c - PAD;
        float cv = 0.f, xv = 0.f;
        if ((unsigned)gy < (unsigned)HH && (unsigned)gx < (unsigned)WW) {
            long gg = (long)gy * WW + gx;
            cv = cp[gg]; xv = xp[gg];
        }
        cs[i] = cv; xcs[i] = xv * cv;
    }
    __syncthreads();
    unsigned long long accN[16], accD[16];
#pragma unroll
    for (int q = 0; q < 16; q++) { accN[q] = 0ULL; accD[q] = 0ULL; }
#pragma unroll
    for (int ky = 0; ky < 5; ky++)
#pragma unroll
        for (int kx = 0; kx < 5; kx++) {
            float cv = cs[(ty + ky) * SW + tx + kx];
            float xc = xcs[(ty + ky) * SW + tx + kx];
            unsigned long long c2 = pack2(cv, cv), x2 = pack2(xc, xc);
            const float* wr = &ws[ky * 5 + kx][0];
#pragma unroll
            for (int q = 0; q < 8; q++) {
                ulonglong2 wv = *reinterpret_cast<const ulonglong2*>(wr + q * 4);
                ffma2(accN[2 * q], wv.x, x2);     ffma2(accD[2 * q], wv.x, c2);
                ffma2(accN[2 * q + 1], wv.y, x2); ffma2(accD[2 * q + 1], wv.y, c2);
            }
        }
    unsigned xcw[16], cw[16];
#pragma unroll
    for (int q = 0; q < 16; q++) {
        float n0, n1, d0, d1;
        unpack2(accN[q], n0, n1); unpack2(accD[q], d0, d1);
        const int co = 2 * q;
        float x0 = n0 / (d0 + EPSF) + bias[co], c0 = d0 * winv[co];
        float x1 = n1 / (d1 + EPSF) + bias[co + 1], c1 = d1 * winv[co + 1];
        xcw[q] = bfp(x0 * c0, x1 * c1);
        cw[q] = bfp(c0, c1);
    }
    char* ob = out + ((long)b * PLANE + (long)(by + ty) * WW + bx + tx) * 128;
    *(uint4*)(ob)      = make_uint4(xcw[0], xcw[1], xcw[2], xcw[3]);
    *(uint4*)(ob + 16) = make_uint4(xcw[4], xcw[5], xcw[6], xcw[7]);
    *(uint4*)(ob + 32) = make_uint4(xcw[8], xcw[9], xcw[10], xcw[11]);
    *(uint4*)(ob + 48) = make_uint4(xcw[12], xcw[13], xcw[14], xcw[15]);
    *(uint4*)(ob + 64) = make_uint4(cw[0], cw[1], cw[2], cw[3]);
    *(uint4*)(ob + 80) = make_uint4(cw[4], cw[5], cw[6], cw[7]);
    *(uint4*)(ob + 96) = make_uint4(cw[8], cw[9], cw[10], cw[11]);
    *(uint4*)(ob + 112) = make_uint4(cw[12], cw[13], cw[14], cw[15]);
}

// ---------- packed bf16 tensor-core encoder nconv: 5x5, 32->32 ----------
template <int HH, int WW>
__global__ __launch_bounds__(256, 2)
void nconv_mma_p(const char* __restrict__ in, const unsigned short* __restrict__ wp,
                 const float* __restrict__ bias, const float* __restrict__ winv,
                 char* __restrict__ out) {
    constexpr int KS = 5, PAD = 2, SW = 36, SH = 12, NS = SH * SW, NS32 = NS * 32;
    constexpr int NCH = 2, WALLB = NCH * 25 * 1024;
    constexpr long PLANE = (long)HH * WW;
    extern __shared__ char dsmc[];
    char* inbuf = dsmc;                 // 2 bufs x (pxc NS32 + pc NS32)
    char* wsb = dsmc + 2 * 2 * NS32;    // WALLB

    const int tid = threadIdx.x, wy = tid >> 5, lane = tid & 31;
    const int g = lane >> 2, t = lane & 3;
    const int bx = blockIdx.x * 32, by = blockIdx.y * 8, bz = blockIdx.z;

    const char* inb = in + (long)bz * PLANE * 128;
    const unsigned in_s = (unsigned)__cvta_generic_to_shared(inbuf);
    const unsigned ws_s = (unsigned)__cvta_generic_to_shared(wsb);

    auto stage_in = [&](int ch, int buf) {
        const unsigned dstb = in_s + buf * (2 * NS32);
        for (int i = tid; i < NS * 4; i += 256) {
            const int p = i >> 2, q = i & 3, h = q & 1, tz = q >> 1;
            const int r = p / SW, c = p - r * SW;
            const int gy = by + r - PAD, gx = bx + c - PAD;
            const bool v = (unsigned)gy < (unsigned)HH && (unsigned)gx < (unsigned)WW;
            const long gp = v ? (long)gy * WW + gx : 0;
            unsigned dst = dstb + tz * NS32 + p * 32 + ((h ^ ((p >> 2) & 1)) << 4);
            cp_async16z(dst, inb + gp * 128 + tz * 64 + ch * 32 + h * 16, v);
        }
    };

    for (int i = tid; i < WALLB / 16; i += 256)
        cp_async16(ws_s + i * 16, (const char*)wp + i * 16);
    stage_in(0, 0);
    cp_commit();

    float accN[2][4][4] = {}, accD[2][4][4] = {};
#pragma unroll 1
    for (int ch = 0; ch < NCH; ch++) {
        cp_wait<0>();
        __syncthreads();
        if (ch + 1 < NCH) { stage_in(ch + 1, (ch + 1) & 1); cp_commit(); }
        const unsigned* wq = reinterpret_cast<const unsigned*>(wsb) + ch * 25 * 256;
        const unsigned pxc_s = in_s + (ch & 1) * (2 * NS32);
        mma_taps_bf16<KS, SW>(wq, pxc_s, pxc_s + NS32, wy, lane, accN, accD);
    }
    epi_packed(accN, accD, bias, winv, out, PLANE, WW, bz, by + wy, bx, g, t);
}

// ---- packed bf16 decoder nconv: 3x3, 64->32, cat + up2; optional fused 1x1 ----
template <int HH, int WW, bool FUSE>
__global__ __launch_bounds__(256, 2)
void nconv_cat_mma_p(const char* __restrict__ in0, int half0,
                     const char* __restrict__ in1, int half1,
                     const unsigned short* __restrict__ wp,
                     const float* __restrict__ bias, const float* __restrict__ winv,
                     char* __restrict__ out,
                     const float* __restrict__ w7, const float* __restrict__ b7,
                     float* __restrict__ fout) {
    constexpr int KS = 3, PAD = 1, SW = 34, SH = 10, NS = SH * SW, NS32 = NS * 32;
    constexpr int NCH = 4, WALLB = NCH * 9 * 1024;
    constexpr int W2 = WW / 2;
    constexpr long PLANE = (long)HH * WW;
    extern __shared__ char dsmc[];
    char* inbuf = dsmc;
    char* wsb = dsmc + 2 * 2 * NS32;

    const int tid = threadIdx.x, wy = tid >> 5, lane = tid & 31;
    const int g = lane >> 2, t = lane & 3;
    const int bx = blockIdx.x * 32, by = blockIdx.y * 8, bz = blockIdx.z;

    const unsigned in_s = (unsigned)__cvta_generic_to_shared(inbuf);
    const unsigned ws_s = (unsigned)__cvta_generic_to_shared(wsb);

    auto stage_in = [&](int ch, int buf) {
        const int grp = ch >> 1;
        const char* src = (grp ? in1 : in0);
        const int half = grp ? half1 : half0;
        const long plane = half ? (long)(HH / 2) * W2 : PLANE;
        const char* sb = src + (long)bz * plane * 128;
        const int chl = ch & 1;
        const unsigned dstb = in_s + buf * (2 * NS32);
        for (int i = tid; i < NS * 4; i += 256) {
            const int p = i >> 2, q = i & 3, h = q & 1, tz = q >> 1;
            const int r = p / SW, c = p - r * SW;
            const int gy = by + r - PAD, gx = bx + c - PAD;
            const bool v = (unsigned)gy < (unsigned)HH && (unsigned)gx < (unsigned)WW;
            const long gp = v ? (half ? (long)(gy >> 1) * W2 + (gx >> 1)
                                      : (long)gy * WW + gx) : 0;
            unsigned dst = dstb + tz * NS32 + p * 32 + ((h ^ ((p >> 2) & 1)) << 4);
            cp_async16z(dst, sb + gp * 128 + tz * 64 + chl * 32 + h * 16, v);
        }
    };

    for (int i = tid; i < WALLB / 16; i += 256)
        cp_async16(ws_s + i * 16, (const char*)wp + i * 16);
    stage_in(0, 0);
    cp_commit();

    float accN[2][4][4] = {}, accD[2][4][4] = {};
#pragma unroll 1
    for (int ch = 0; ch < NCH; ch++) {
        cp_wait<0>();
        __syncthreads();
        if (ch + 1 < NCH) { stage_in(ch + 1, (ch + 1) & 1); cp_commit(); }
        const unsigned* wq = reinterpret_cast<const unsigned*>(wsb) + ch * 9 * 256;
        const unsigned pxc_s = in_s + (ch & 1) * (2 * NS32);
        mma_taps_bf16<KS, SW>(wq, pxc_s, pxc_s + NS32, wy, lane, accN, accD);
    }

    const int y = by + wy;
    if (!FUSE) {
        epi_packed(accN, accD, bias, winv, out, PLANE, WW, bz, y, bx, g, t);
    } else {
        float w7a[4], w7b[4];
#pragma unroll
        for (int nf = 0; nf < 4; nf++) {
            w7a[nf] = __ldg(w7 + nf * 8 + 2 * t);
            w7b[nf] = __ldg(w7 + nf * 8 + 2 * t + 1);
        }
        const float b7v = __ldg(b7);
#pragma unroll
        for (int mf = 0; mf < 2; mf++) {
            float ns0 = 0.f, ds0 = 0.f, ns1 = 0.f, ds1 = 0.f;
#pragma unroll
            for (int nf = 0; nf < 4; nf++) {
                const int co = nf * 8 + 2 * t;
                float* n = accN[mf][nf];
                float* d = accD[mf][nf];
                float x00 = n[0] / (d[0] + EPSF) + bias[co],     c00 = d[0] * winv[co];
                float x01 = n[1] / (d[1] + EPSF) + bias[co + 1], c01 = d[1] * winv[co + 1];
                float x10 = n[2] / (d[2] + EPSF) + bias[co],     c10 = d[2] * winv[co];
                float x11 = n[3] / (d[3] + EPSF) + bias[co + 1], c11 = d[3] * winv[co + 1];
                ns0 += w7a[nf] * x00 * c00 + w7b[nf] * x01 * c01;
                ds0 += w7a[nf] * c00 + w7b[nf] * c01;
                ns1 += w7a[nf] * x10 * c10 + w7b[nf] * x11 * c11;
                ds1 += w7a[nf] * c10 + w7b[nf] * c11;
            }
#pragma unroll
            for (int s = 1; s <= 2; s <<= 1) {
                ns0 += __shfl_xor_sync(0xffffffffu, ns0, s);
                ds0 += __shfl_xor_sync(0xffffffffu, ds0, s);
                ns1 += __shfl_xor_sync(0xffffffffu, ns1, s);
                ds1 += __shfl_xor_sync(0xffffffffu, ds1, s);
            }
            if (t == 0) {
                const long base = (long)bz * PLANE + (long)y * WW + bx + mf * 16 + g;
                fout[base]     = ns0 / (ds0 + EPSF) + b7v;
                fout[base + 8] = ns1 / (ds1 + EPSF) + b7v;
            }
        }
    }
}

// ---------------- launch ----------------
static constexpr int SMEM_ENC = 4 * 432 * 32 + 2 * 25 * 1024;  // 55296 + 51200 = 106496
static constexpr int SMEM_DEC = 4 * 340 * 32 + 4 * 9 * 1024;   // 43520 + 36864 = 80384

extern "C" void kernel_launch(void* const* d_in, const int* in_sizes, int n_in,
                              void* d_out, int out_size) {
    const float* x  = (const float*)d_in[0];
    const float* w1 = (const float*)d_in[1];  const float* b1 = (const float*)d_in[2];
    const float* w2 = (const float*)d_in[3];  const float* b2 = (const float*)d_in[4];
    const float* w3 = (const float*)d_in[5];  const float* b3 = (const float*)d_in[6];
    const float* w4 = (const float*)d_in[7];  const float* b4 = (const float*)d_in[8];
    const float* w5 = (const float*)d_in[9];  const float* b5 = (const float*)d_in[10];
    const float* w6 = (const float*)d_in[11]; const float* b6 = (const float*)d_in[12];
    const float* w7 = (const float*)d_in[13]; const float* b7 = (const float*)d_in[14];

    float* pool = nullptr;
    cudaGetSymbolAddress((void**)&pool, g_pool);

    char* F512a = (char*)(pool);
    char* F512b = (char*)(pool + N512);
    char* F512s = (char*)(pool + 2 * N512);
    char* F256a = (char*)(pool + 3 * N512);
    char* F256b = (char*)(pool + 3 * N512 + N256);
    char* F256s = (char*)(pool + 3 * N512 + 2 * N256);
    char* D256  = (char*)(pool + 3 * N512 + 3 * N256);
    char* F128a = (char*)(pool + 3 * N512 + 4 * N256);
    char* F128s = (char*)(pool + 3 * N512 + 4 * N256 + N128);
    char* D128  = (char*)(pool + 3 * N512 + 4 * N256 + 2 * N128);
    char* F64a  = (char*)(pool + 3 * N512 + 4 * N256 + 3 * N128);
    char* F64b  = (char*)(pool + 3 * N512 + 4 * N256 + 3 * N128 + N64);
    float* WS   = pool + 3 * N512 + 4 * N256 + 3 * N128 + 2 * N64;
    __nv_bfloat16* PW2 = (__nv_bfloat16*)(WS + 4096);
    __nv_bfloat16* PW3 = (__nv_bfloat16*)(WS + 4096 + 12800);
    __nv_bfloat16* PW4 = (__nv_bfloat16*)(WS + 4096 + 2 * 12800);
    __nv_bfloat16* PW5 = (__nv_bfloat16*)(WS + 4096 + 2 * 12800 + 9216);
    __nv_bfloat16* PW6 = (__nv_bfloat16*)(WS + 4096 + 2 * 12800 + 2 * 9216);

    cudaFuncSetAttribute(nconv_mma_p<512, 512>, cudaFuncAttributeMaxDynamicSharedMemorySize, SMEM_ENC);
    cudaFuncSetAttribute(nconv_mma_p<256, 256>, cudaFuncAttributeMaxDynamicSharedMemorySize, SMEM_ENC);
    cudaFuncSetAttribute(nconv_mma_p<128, 128>, cudaFuncAttributeMaxDynamicSharedMemorySize, SMEM_ENC);
    cudaFuncSetAttribute(nconv_mma_p<64, 64>,   cudaFuncAttributeMaxDynamicSharedMemorySize, SMEM_ENC);
    cudaFuncSetAttribute(nconv_cat_mma_p<128, 128, false>, cudaFuncAttributeMaxDynamicSharedMemorySize, SMEM_DEC);
    cudaFuncSetAttribute(nconv_cat_mma_p<256, 256, false>, cudaFuncAttributeMaxDynamicSharedMemorySize, SMEM_DEC);
    cudaFuncSetAttribute(nconv_cat_mma_p<512, 512, true>,  cudaFuncAttributeMaxDynamicSharedMemorySize, SMEM_DEC);

    const long HW = 512L * 512;

    wsum_kernel<<<7, 32>>>(w1, w2, w3, w4, w5, w6, w7, WS);
    prep_w_bf16<<<100, 256>>>(w2, PW2, 32, 25, 25600);
    prep_w_bf16<<<100, 256>>>(w3, PW3, 32, 25, 25600);
    prep_w_bf16<<<72, 256>>>(w4, PW4, 64, 9, 18432);
    prep_w_bf16<<<72, 256>>>(w5, PW5, 64, 9, 18432);
    prep_w_bf16<<<72, 256>>>(w6, PW6, 64, 9, 18432);

    // Encoder @512
    nconv_l1<512, 512><<<dim3(16, 64, 2), 256>>>(x, x + HW, 2 * HW, w1, b1, WS, F512a);
    nconv_mma_p<512, 512><<<dim3(16, 64, 2), 256, SMEM_ENC>>>(
        F512a, (const unsigned short*)PW2, b2, WS + 32, F512b);
    nconv_mma_p<512, 512><<<dim3(16, 64, 2), 256, SMEM_ENC>>>(
        F512b, (const unsigned short*)PW3, b3, WS + 64, F512s);

    // Down 1 @256
    pool_p<<<(int)((2L * 256 * 256 * 2 + 255) / 256), 256>>>(F512s, F256a, 256, 256);
    nconv_mma_p<256, 256><<<dim3(8, 32, 2), 256, SMEM_ENC>>>(
        F256a, (const unsigned short*)PW2, b2, WS + 32, F256b);
    nconv_mma_p<256, 256><<<dim3(8, 32, 2), 256, SMEM_ENC>>>(
        F256b, (const unsigned short*)PW3, b3, WS + 64, F256s);

    // Down 2 @128
    pool_p<<<(int)((2L * 128 * 128 * 2 + 255) / 256), 256>>>(F256s, F128a, 128, 128);
    nconv_mma_p<128, 128><<<dim3(4, 16, 2), 256, SMEM_ENC>>>(
        F128a, (const unsigned short*)PW2, b2, WS + 32, F128s);

    // Down 3 @64
    pool_p<<<(int)((2L * 64 * 64 * 2 + 255) / 256), 256>>>(F128s, F64a, 64, 64);
    nconv_mma_p<64, 64><<<dim3(2, 8, 2), 256, SMEM_ENC>>>(
        F64a, (const unsigned short*)PW2, b2, WS + 32, F64b);

    // Decoder
    nconv_cat_mma_p<128, 128, false><<<dim3(4, 16, 2), 256, SMEM_DEC>>>(
        F128s, 0, F64b, 1, (const unsigned short*)PW4, b4, WS + 96, D128,
        nullptr, nullptr, nullptr);
    nconv_cat_mma_p<256, 256, false><<<dim3(8, 32, 2), 256, SMEM_DEC>>>(
        F256s, 0, D128, 1, (const unsigned short*)PW5, b5, WS + 128, D256,
        nullptr, nullptr, nullptr);
    nconv_cat_mma_p<512, 512, true><<<dim3(16, 64, 2), 256, SMEM_DEC>>>(
        D256, 1, F512s, 0, (const unsigned short*)PW6, b6, WS + 160, nullptr,
        w7, b7, (float*)d_out);
}